// round 7
// baseline (speedup 1.0000x reference)
#include <cuda_runtime.h>
#include <math.h>

// Problem constants
#define BSZ  64
#define TLEN 512
#define FDIM 512
#define HDIM 1024
#define G4H  4096   // 4*H
#define NCTA 128    // persistent grid size (<= 148 SMs, all co-resident)

// ---------------------------------------------------------------------------
// Scratch (device globals: allowed; cudaMalloc is not)
// ---------------------------------------------------------------------------
__device__ float g_pre0[(size_t)TLEN * BSZ * G4H];  // [t][b][4H]
__device__ float g_h0[2][BSZ * HDIM];
__device__ float g_h1[2][BSZ * HDIM];
__device__ float g_c0[BSZ * HDIM];
__device__ float g_c1[BSZ * HDIM];

// Grid barrier state (monotone generation counter: survives graph replays)
__device__ unsigned g_bar_count = 0;
__device__ unsigned g_bar_gen   = 0;

// ---------------------------------------------------------------------------
// Software grid barrier (sense-free, generation-based).
// All NCTA CTAs are guaranteed co-resident (grid <= SM count, 1 CTA/SM).
// ---------------------------------------------------------------------------
__device__ __forceinline__ void grid_bar(unsigned& gen) {
    __syncthreads();
    if (threadIdx.x == 0) {
        __threadfence();                           // release prior writes
        unsigned t = atomicAdd(&g_bar_count, 1u);
        if (t == NCTA - 1) {
            atomicExch(&g_bar_count, 0u);          // reset for next barrier
            __threadfence();
            atomicAdd(&g_bar_gen, 1u);             // release
        } else {
            while (atomicAdd(&g_bar_gen, 0u) <= gen) {
                __nanosleep(40);
            }
        }
        __threadfence();                           // acquire
    }
    gen++;
    __syncthreads();
}

// ---------------------------------------------------------------------------
// Precompute: g_pre0[t][b][n] = x[b,t,:] @ W_ih_0[n,:] + b_ih_0[n] + b_hh_0[n]
// Tiled NT GEMM: M = B*T = 32768 (row m = b*T + t), N = 4096, K = 512.
// (Validated in round 5; left unchanged.)
// ---------------------------------------------------------------------------
__global__ __launch_bounds__(256) void pre_gemm_kernel(
    const float* __restrict__ X,      // [B*T, F] row-major
    const float* __restrict__ W,      // [4H, F] row-major
    const float* __restrict__ bi,
    const float* __restrict__ bh)
{
    __shared__ float As[32 * 65];
    __shared__ float Bs[32 * 65];

    const int m0 = blockIdx.y * 64;
    const int n0 = blockIdx.x * 64;
    const int tid = threadIdx.x;
    const int ty = tid >> 4;
    const int tx = tid & 15;

    float acc[4][4] = {};

    for (int k0 = 0; k0 < FDIM; k0 += 32) {
        #pragma unroll
        for (int i = 0; i < 8; i++) {
            int idx = i * 256 + tid;
            int kk = idx & 31;
            int r  = idx >> 5;
            As[kk * 65 + r] = X[(size_t)(m0 + r) * FDIM + k0 + kk];
            Bs[kk * 65 + r] = W[(size_t)(n0 + r) * FDIM + k0 + kk];
        }
        __syncthreads();

        #pragma unroll
        for (int kk = 0; kk < 32; kk++) {
            float a[4], b[4];
            #pragma unroll
            for (int i = 0; i < 4; i++) a[i] = As[kk * 65 + ty * 4 + i];
            #pragma unroll
            for (int j = 0; j < 4; j++) b[j] = Bs[kk * 65 + tx * 4 + j];
            #pragma unroll
            for (int i = 0; i < 4; i++)
                #pragma unroll
                for (int j = 0; j < 4; j++)
                    acc[i][j] += a[i] * b[j];
        }
        __syncthreads();
    }

    #pragma unroll
    for (int i = 0; i < 4; i++) {
        int m = m0 + ty * 4 + i;
        int b = m >> 9;               // m / TLEN
        int t = m & 511;              // m % TLEN
        float* dst = &g_pre0[((size_t)t * BSZ + b) * G4H];
        #pragma unroll
        for (int j = 0; j < 4; j++) {
            int n = n0 + tx * 4 + j;
            dst[n] = acc[i][j] + bi[n] + bh[n];
        }
    }
}

// ---------------------------------------------------------------------------
// Accumulate: CTA tile M=64 (batch) x N=32 (8 hidden x 4 gates), K=HDIM.
// Column c: gate g=c>>3, hidden j=j0+(c&7), weight row n=g*HDIM+j.
// Tiles stored row-major [row][k] with pitch 36 floats (144 B: 16B-aligned
// rows, contiguous conflict-free stores). Inner loop vectorized: float4 over
// k -> 6 LDS.128 + 32 FFMA per 4 k's (FFMA-bound, not crossbar-bound).
// ---------------------------------------------------------------------------
#define APITCH 36
#define BPITCH 36

__device__ __forceinline__ void accumulate_K(
    float acc[4][2],
    const float* __restrict__ A,      // [64, HDIM] row-major (h state)
    const float* __restrict__ W,      // [4H, HDIM] row-major
    int j0, int tid, int ty, int tx,
    float* As, float* Bs)             // As[64*APITCH], Bs[32*BPITCH], align16
{
    for (int k0 = 0; k0 < HDIM; k0 += 32) {
        // A tile: 64 rows x 32 k. Global coalesced (k contiguous per warp),
        // smem store contiguous within row -> conflict-free.
        #pragma unroll
        for (int i = 0; i < 8; i++) {
            int idx = i * 256 + tid;
            int kk = idx & 31;
            int r  = idx >> 5;
            As[r * APITCH + kk] = A[r * HDIM + k0 + kk];
        }
        // B tile: 32 gate-columns x 32 k.
        #pragma unroll
        for (int i = 0; i < 4; i++) {
            int idx = i * 256 + tid;
            int kk = idx & 31;
            int c  = idx >> 5;
            int n  = ((c >> 3) << 10) + j0 + (c & 7);
            Bs[c * BPITCH + kk] = W[(size_t)n * HDIM + k0 + kk];
        }
        __syncthreads();

        #pragma unroll
        for (int q = 0; q < 8; q++) {
            float4 b0 = *(const float4*)&Bs[(tx * 2 + 0) * BPITCH + q * 4];
            float4 b1 = *(const float4*)&Bs[(tx * 2 + 1) * BPITCH + q * 4];
            #pragma unroll
            for (int i = 0; i < 4; i++) {
                float4 a = *(const float4*)&As[(ty * 4 + i) * APITCH + q * 4];
                acc[i][0] += a.x * b0.x + a.y * b0.y + a.z * b0.z + a.w * b0.w;
                acc[i][1] += a.x * b1.x + a.y * b1.y + a.z * b1.z + a.w * b1.w;
            }
        }
        __syncthreads();
    }
}

__device__ __forceinline__ float sigf(float x) {
    return 1.f / (1.f + expf(-x));
}

// ---------------------------------------------------------------------------
// Persistent recurrence kernel: all 512 steps, both layers, ONE launch.
// 128 CTAs x 256 threads. CTA owns hidden units j0..j0+7 (both layers).
// ONE grid barrier per step (between layer0 and layer1): layer1(t) and
// layer0(t+1) touch disjoint buffers, and the next step's barrier
// transitively orders all cross-CTA dependencies.
// ---------------------------------------------------------------------------
__global__ __launch_bounds__(256) void lstm_persistent_kernel(
    const float* __restrict__ Whh0,
    const float* __restrict__ Wih1, const float* __restrict__ Whh1,
    const float* __restrict__ bi1,  const float* __restrict__ bh1,
    float* __restrict__ out)
{
    __shared__ __align__(16) float As[64 * APITCH];
    __shared__ __align__(16) float Bs[32 * BPITCH];
    __shared__ float gbuf[64 * 33];

    const int j0  = blockIdx.x * 8;
    const int tid = threadIdx.x;
    const int ty  = tid >> 4;
    const int tx  = tid & 15;

    unsigned gen = atomicAdd(&g_bar_gen, 0u);  // stable pre-launch value

    // ---- init own state slice (columns j0..j0+7, all b) ----
    for (int u = tid; u < 64 * 8; u += 256) {
        int b = u >> 3, jj = u & 7;
        int idx = b * HDIM + j0 + jj;
        g_h0[0][idx] = 0.f;
        g_h1[0][idx] = 0.f;
        g_c0[idx]    = 0.f;
        g_c1[idx]    = 0.f;
    }
    grid_bar(gen);

    // ---- preload layer-1 bias sums into registers ----
    float bsum[2];
    #pragma unroll
    for (int j = 0; j < 2; j++) {
        int c = tx * 2 + j;
        int n = ((c >> 3) << 10) + j0 + (c & 7);
        bsum[j] = bi1[n] + bh1[n];
    }

    for (int t = 0; t < TLEN; t++) {
        // ======================= layer 0 =======================
        const float* hp = g_h0[t & 1];
        float*       hn = g_h0[(t + 1) & 1];

        // prefetch input-projection values (HBM latency hides under GEMM)
        float prev[4][2];
        {
            const float* pre = &g_pre0[(size_t)t * BSZ * G4H];
            #pragma unroll
            for (int i = 0; i < 4; i++) {
                int b = ty * 4 + i;
                #pragma unroll
                for (int j = 0; j < 2; j++) {
                    int c = tx * 2 + j;
                    int n = ((c >> 3) << 10) + j0 + (c & 7);
                    prev[i][j] = pre[(size_t)b * G4H + n];
                }
            }
        }

        float acc[4][2] = {};
        accumulate_K(acc, hp, Whh0, j0, tid, ty, tx, As, Bs);

        #pragma unroll
        for (int i = 0; i < 4; i++) {
            int b = ty * 4 + i;
            #pragma unroll
            for (int j = 0; j < 2; j++) {
                int c = tx * 2 + j;
                gbuf[b * 33 + c] = acc[i][j] + prev[i][j];
            }
        }
        __syncthreads();

        #pragma unroll
        for (int u = 0; u < 2; u++) {
            int cell = tid * 2 + u;
            int b  = cell >> 3;
            int jj = cell & 7;
            float ig = gbuf[b * 33 + jj];
            float fg = gbuf[b * 33 + 8 + jj];
            float gg = gbuf[b * 33 + 16 + jj];
            float og = gbuf[b * 33 + 24 + jj];
            int j = j0 + jj;
            float c_old = g_c0[b * HDIM + j];
            float cn = sigf(fg) * c_old + sigf(ig) * tanhf(gg);
            float hv = sigf(og) * tanhf(cn);
            g_c0[b * HDIM + j] = cn;
            hn[b * HDIM + j]   = hv;
        }
        grid_bar(gen);   // all of h0(t) and h1(t-1) visible before layer 1

        // ======================= layer 1 =======================
        const float* h0t = g_h0[(t + 1) & 1];
        const float* h1p = g_h1[t & 1];
        float*       h1n = g_h1[(t + 1) & 1];

        float acc2[4][2] = {};
        accumulate_K(acc2, h0t, Wih1, j0, tid, ty, tx, As, Bs);
        accumulate_K(acc2, h1p, Whh1, j0, tid, ty, tx, As, Bs);

        #pragma unroll
        for (int i = 0; i < 4; i++) {
            int b = ty * 4 + i;
            #pragma unroll
            for (int j = 0; j < 2; j++) {
                int c = tx * 2 + j;
                gbuf[b * 33 + c] = acc2[i][j] + bsum[j];
            }
        }
        __syncthreads();

        #pragma unroll
        for (int u = 0; u < 2; u++) {
            int cell = tid * 2 + u;
            int b  = cell >> 3;
            int jj = cell & 7;
            float ig = gbuf[b * 33 + jj];
            float fg = gbuf[b * 33 + 8 + jj];
            float gg = gbuf[b * 33 + 16 + jj];
            float og = gbuf[b * 33 + 24 + jj];
            int j = j0 + jj;
            float c_old = g_c1[b * HDIM + j];
            float cn = sigf(fg) * c_old + sigf(ig) * tanhf(gg);
            float hv = sigf(og) * tanhf(cn);
            g_c1[b * HDIM + j] = cn;
            h1n[b * HDIM + j]  = hv;
            out[((size_t)b * TLEN + t) * HDIM + j] = hv;   // out[b, t, j]
        }
        // no trailing barrier: layer0(t+1) touches only buffers disjoint
        // from layer1(t); the next step's barrier orders everything else.
        __syncthreads();   // protect shared As/Bs reuse within the CTA
    }

    // ---- pack final states (own slice only; T even -> buffers [0]) ----
    const size_t BH   = (size_t)BSZ * HDIM;
    const size_t base = (size_t)BSZ * TLEN * HDIM;
    for (int u = tid; u < 64 * 8; u += 256) {
        int b = u >> 3, jj = u & 7;
        int idx = b * HDIM + j0 + jj;
        out[base + idx]          = g_h0[0][idx];
        out[base + BH + idx]     = g_h1[0][idx];
        out[base + 2 * BH + idx] = g_c0[idx];
        out[base + 3 * BH + idx] = g_c1[idx];
    }
}

// ---------------------------------------------------------------------------
// Launch: 2 kernel nodes only (graph-capturable, tiny graph -> no upload pool)
// ---------------------------------------------------------------------------
extern "C" void kernel_launch(void* const* d_in, const int* in_sizes, int n_in,
                              void* d_out, int out_size)
{
    (void)in_sizes; (void)n_in; (void)out_size;
    const float* x    = (const float*)d_in[0];
    const float* Wih0 = (const float*)d_in[1];
    const float* Whh0 = (const float*)d_in[2];
    const float* bih0 = (const float*)d_in[3];
    const float* bhh0 = (const float*)d_in[4];
    const float* Wih1 = (const float*)d_in[5];
    const float* Whh1 = (const float*)d_in[6];
    const float* bih1 = (const float*)d_in[7];
    const float* bhh1 = (const float*)d_in[8];
    float* out = (float*)d_out;

    dim3 pre_grid(G4H / 64, (BSZ * TLEN) / 64);   // 64 x 512 CTAs
    pre_gemm_kernel<<<pre_grid, 256>>>(x, Wih0, bih0, bhh0);

    lstm_persistent_kernel<<<NCTA, 256>>>(Whh0, Wih1, Whh1, bih1, bhh1, out);
}

// round 8
// speedup vs baseline: 1.8348x; 1.8348x over previous
#include <cuda_runtime.h>
#include <math.h>
#include <stdint.h>

// Problem constants
#define BSZ  64
#define TLEN 512
#define FDIM 512
#define HDIM 1024
#define G4H  4096   // 4*H
#define NCTA 128    // persistent grid size (<= 148 SMs, all co-resident)

#define AP 36       // smem pitch (floats) for A tiles: (36g+t)&31 = 4g+t -> conflict-free frags
#define BP 36       // smem pitch for B tiles

// ---------------------------------------------------------------------------
// Scratch (device globals: allowed; cudaMalloc is not)
// ---------------------------------------------------------------------------
__device__ float g_pre0[(size_t)TLEN * BSZ * G4H];  // [t][b][4H]
__device__ float g_h0[2][BSZ * HDIM];
__device__ float g_h1[2][BSZ * HDIM];
__device__ float g_c0[BSZ * HDIM];
__device__ float g_c1[BSZ * HDIM];

// Grid barrier state (monotone generation counter: survives graph replays)
__device__ unsigned g_bar_count = 0;
__device__ unsigned g_bar_gen   = 0;

// ---------------------------------------------------------------------------
// Software grid barrier (sense-free, generation-based).
// ---------------------------------------------------------------------------
__device__ __forceinline__ void grid_bar(unsigned& gen) {
    __syncthreads();
    if (threadIdx.x == 0) {
        __threadfence();
        unsigned t = atomicAdd(&g_bar_count, 1u);
        if (t == NCTA - 1) {
            atomicExch(&g_bar_count, 0u);
            __threadfence();
            atomicAdd(&g_bar_gen, 1u);
        } else {
            while (atomicAdd(&g_bar_gen, 0u) <= gen) {
                __nanosleep(40);
            }
        }
        __threadfence();
    }
    gen++;
    __syncthreads();
}

// ---------------------------------------------------------------------------
// Precompute: g_pre0[t][b][n] = x[b,t,:] @ W_ih_0[n,:] + b_ih_0[n] + b_hh_0[n]
// (Validated in earlier rounds; unchanged.)
// ---------------------------------------------------------------------------
__global__ __launch_bounds__(256) void pre_gemm_kernel(
    const float* __restrict__ X,      // [B*T, F] row-major
    const float* __restrict__ W,      // [4H, F] row-major
    const float* __restrict__ bi,
    const float* __restrict__ bh)
{
    __shared__ float As[32 * 65];
    __shared__ float Bs[32 * 65];

    const int m0 = blockIdx.y * 64;
    const int n0 = blockIdx.x * 64;
    const int tid = threadIdx.x;
    const int ty = tid >> 4;
    const int tx = tid & 15;

    float acc[4][4] = {};

    for (int k0 = 0; k0 < FDIM; k0 += 32) {
        #pragma unroll
        for (int i = 0; i < 8; i++) {
            int idx = i * 256 + tid;
            int kk = idx & 31;
            int r  = idx >> 5;
            As[kk * 65 + r] = X[(size_t)(m0 + r) * FDIM + k0 + kk];
            Bs[kk * 65 + r] = W[(size_t)(n0 + r) * FDIM + k0 + kk];
        }
        __syncthreads();

        #pragma unroll
        for (int kk = 0; kk < 32; kk++) {
            float a[4], b[4];
            #pragma unroll
            for (int i = 0; i < 4; i++) a[i] = As[kk * 65 + ty * 4 + i];
            #pragma unroll
            for (int j = 0; j < 4; j++) b[j] = Bs[kk * 65 + tx * 4 + j];
            #pragma unroll
            for (int i = 0; i < 4; i++)
                #pragma unroll
                for (int j = 0; j < 4; j++)
                    acc[i][j] += a[i] * b[j];
        }
        __syncthreads();
    }

    #pragma unroll
    for (int i = 0; i < 4; i++) {
        int m = m0 + ty * 4 + i;
        int b = m >> 9;
        int t = m & 511;
        float* dst = &g_pre0[((size_t)t * BSZ + b) * G4H];
        #pragma unroll
        for (int j = 0; j < 4; j++) {
            int n = n0 + tx * 4 + j;
            dst[n] = acc[i][j] + bi[n] + bh[n];
        }
    }
}

// ---------------------------------------------------------------------------
// tf32 helpers
// ---------------------------------------------------------------------------
__device__ __forceinline__ uint32_t f2tf32(float x) {
    uint32_t r;
    asm("cvt.rna.tf32.f32 %0, %1;" : "=r"(r) : "f"(x));
    return r;
}

// Split a float4 into tf32 hi + tf32 lo, store both as float4 to smem.
__device__ __forceinline__ void split4(float* hi_p, float* lo_p, float4 v) {
    float xs[4] = {v.x, v.y, v.z, v.w};
    float4 hv, lv;
    float* hp = &hv.x;
    float* lp = &lv.x;
    #pragma unroll
    for (int i = 0; i < 4; i++) {
        uint32_t h = f2tf32(xs[i]);
        float hf = __uint_as_float(h);
        hp[i] = hf;
        lp[i] = __uint_as_float(f2tf32(xs[i] - hf));
    }
    *(float4*)hi_p = hv;
    *(float4*)lo_p = lv;
}

__device__ __forceinline__ void mma8(float c[4],
    uint32_t a0, uint32_t a1, uint32_t a2, uint32_t a3,
    uint32_t b0, uint32_t b1)
{
    asm volatile(
        "mma.sync.aligned.m16n8k8.row.col.f32.tf32.tf32.f32 "
        "{%0,%1,%2,%3}, {%4,%5,%6,%7}, {%8,%9}, {%0,%1,%2,%3};"
        : "+f"(c[0]), "+f"(c[1]), "+f"(c[2]), "+f"(c[3])
        : "r"(a0), "r"(a1), "r"(a2), "r"(a3), "r"(b0), "r"(b1));
}

// ---------------------------------------------------------------------------
// 3xTF32 GEMM accumulate: C[64,32] += A[64,K] @ W_rows^T with tile N=32.
// Gate column c: weight row n = (c>>3)*1024 + j0 + (c&7).
// Source switches at chunk `half` (layer1: A0/W0 then A1/W1). K chunk = 32.
// Register-staged LDG prefetch hides L2 latency behind MMA compute.
// ---------------------------------------------------------------------------
__device__ __forceinline__ void gemm3tf32(
    float C[2][4],
    const float* __restrict__ A0, const float* __restrict__ W0,
    const float* __restrict__ A1, const float* __restrict__ W1,
    int nchunk, int half, int j0, int tid,
    float* sAhi, float* sAlo, float* sBhi, float* sBlo)
{
    const int w  = tid >> 5;
    const int ln = tid & 31;
    const int g  = ln >> 2;
    const int tg = ln & 3;
    const int mrow = (w & 3) * 16 + g;   // A fragment row
    const int cb   = (w >> 2) * 16;      // gate-column base (two 8-wide tiles)

    // load mapping: A = 64x32 (2 float4/thread), B = 32x32 (1 float4/thread)
    const int arow = tid >> 3;           // 0..31 ; second half +32
    const int ak4  = (tid & 7) * 4;
    const int bn   = ((arow >> 3) << 10) + j0 + (arow & 7);  // weight row for c=arow

    float4 aR0, aR1, bR;

    // prologue: load chunk 0
    {
        const float* A = (0 < half) ? A0 : A1;
        const float* W = (0 < half) ? W0 : W1;
        aR0 = *(const float4*)&A[(size_t)arow * HDIM + ak4];
        aR1 = *(const float4*)&A[(size_t)(arow + 32) * HDIM + ak4];
        bR  = *(const float4*)&W[(size_t)bn * HDIM + ak4];
    }

    for (int p = 0; p < nchunk; p++) {
        // stage current chunk into smem (tf32 hi/lo split)
        split4(&sAhi[arow * AP + ak4],        &sAlo[arow * AP + ak4],        aR0);
        split4(&sAhi[(arow + 32) * AP + ak4], &sAlo[(arow + 32) * AP + ak4], aR1);
        split4(&sBhi[arow * BP + ak4],        &sBlo[arow * BP + ak4],        bR);
        __syncthreads();

        // prefetch next chunk into registers (latency hidden under MMAs)
        if (p + 1 < nchunk) {
            int pn = p + 1;
            const float* A = (pn < half) ? A0 : A1;
            const float* W = (pn < half) ? W0 : W1;
            int k0 = (pn < half ? pn : pn - half) * 32;
            aR0 = *(const float4*)&A[(size_t)arow * HDIM + k0 + ak4];
            aR1 = *(const float4*)&A[(size_t)(arow + 32) * HDIM + k0 + ak4];
            bR  = *(const float4*)&W[(size_t)bn * HDIM + k0 + ak4];
        }

        // compute: 4 k-steps of 8; 2 n-tiles; 3 MMAs each (hi*hi, hi*lo, lo*hi)
        #pragma unroll
        for (int q = 0; q < 4; q++) {
            const int kb = q * 8;
            const float* Ah = &sAhi[mrow * AP + kb + tg];
            const float* Al = &sAlo[mrow * AP + kb + tg];
            uint32_t ah0 = __float_as_uint(Ah[0]);
            uint32_t ah1 = __float_as_uint(Ah[8 * AP]);
            uint32_t ah2 = __float_as_uint(Ah[4]);
            uint32_t ah3 = __float_as_uint(Ah[8 * AP + 4]);
            uint32_t al0 = __float_as_uint(Al[0]);
            uint32_t al1 = __float_as_uint(Al[8 * AP]);
            uint32_t al2 = __float_as_uint(Al[4]);
            uint32_t al3 = __float_as_uint(Al[8 * AP + 4]);
            #pragma unroll
            for (int s = 0; s < 2; s++) {
                const float* Bh = &sBhi[(cb + s * 8 + g) * BP + kb + tg];
                const float* Bl = &sBlo[(cb + s * 8 + g) * BP + kb + tg];
                uint32_t bh0 = __float_as_uint(Bh[0]);
                uint32_t bh1 = __float_as_uint(Bh[4]);
                uint32_t bl0 = __float_as_uint(Bl[0]);
                uint32_t bl1 = __float_as_uint(Bl[4]);
                mma8(C[s], ah0, ah1, ah2, ah3, bh0, bh1);
                mma8(C[s], ah0, ah1, ah2, ah3, bl0, bl1);
                mma8(C[s], al0, al1, al2, al3, bh0, bh1);
            }
        }
        __syncthreads();
    }
}

__device__ __forceinline__ float sigf(float x) {
    return 1.f / (1.f + expf(-x));
}

// ---------------------------------------------------------------------------
// Persistent recurrence kernel: 512 steps, both layers, ONE launch.
// 128 CTAs x 256 threads; CTA owns hidden units j0..j0+7 (both layers).
// One grid barrier per step (between layer0 and layer1) — transitively
// orders everything (buffers touched by layer1(t) and layer0(t+1) disjoint).
// ---------------------------------------------------------------------------
__global__ __launch_bounds__(256, 1) void lstm_persistent_kernel(
    const float* __restrict__ Whh0,
    const float* __restrict__ Wih1, const float* __restrict__ Whh1,
    const float* __restrict__ bi1,  const float* __restrict__ bh1,
    float* __restrict__ out)
{
    __shared__ __align__(16) float sAhi[64 * AP];
    __shared__ __align__(16) float sAlo[64 * AP];
    __shared__ __align__(16) float sBhi[32 * BP];
    __shared__ __align__(16) float sBlo[32 * BP];
    __shared__ float gbuf[64 * 33];

    const int j0  = blockIdx.x * 8;
    const int tid = threadIdx.x;
    const int w   = tid >> 5;
    const int ln  = tid & 31;
    const int g   = ln >> 2;
    const int tg  = ln & 3;
    const int mrow = (w & 3) * 16 + g;
    const int cbase = (w >> 2) * 16;

    unsigned gen = atomicAdd(&g_bar_gen, 0u);

    // ---- init own state slice ----
    for (int u = tid; u < 64 * 8; u += 256) {
        int b = u >> 3, jj = u & 7;
        int idx = b * HDIM + j0 + jj;
        g_h0[0][idx] = 0.f;
        g_h1[0][idx] = 0.f;
        g_c0[idx]    = 0.f;
        g_c1[idx]    = 0.f;
    }
    grid_bar(gen);

    // ---- preload layer-1 bias sums (cell-update mapping) ----
    float bsum[2][4];
    #pragma unroll
    for (int u = 0; u < 2; u++) {
        int jj = (tid * 2 + u) & 7;
        #pragma unroll
        for (int gt = 0; gt < 4; gt++) {
            int n = gt * HDIM + j0 + jj;
            bsum[u][gt] = bi1[n] + bh1[n];
        }
    }

    for (int t = 0; t < TLEN; t++) {
        // ======================= layer 0 =======================
        const float* hp = g_h0[t & 1];
        float*       hn = g_h0[(t + 1) & 1];

        // prefetch input-projection values (cell-update mapping)
        float prev[2][4];
        {
            const float* pre = &g_pre0[(size_t)t * BSZ * G4H];
            #pragma unroll
            for (int u = 0; u < 2; u++) {
                int cell = tid * 2 + u;
                int b = cell >> 3, jj = cell & 7;
                #pragma unroll
                for (int gt = 0; gt < 4; gt++)
                    prev[u][gt] = pre[(size_t)b * G4H + gt * HDIM + j0 + jj];
            }
        }

        float C[2][4] = {};
        gemm3tf32(C, hp, Whh0, hp, Whh0, 32, 32, j0, tid,
                  sAhi, sAlo, sBhi, sBlo);

        // epilogue: MMA fragments -> gbuf
        #pragma unroll
        for (int s = 0; s < 2; s++) {
            int col = cbase + s * 8 + 2 * tg;
            gbuf[mrow * 33 + col]           = C[s][0];
            gbuf[mrow * 33 + col + 1]       = C[s][1];
            gbuf[(mrow + 8) * 33 + col]     = C[s][2];
            gbuf[(mrow + 8) * 33 + col + 1] = C[s][3];
        }
        __syncthreads();

        #pragma unroll
        for (int u = 0; u < 2; u++) {
            int cell = tid * 2 + u;
            int b  = cell >> 3;
            int jj = cell & 7;
            float ig = gbuf[b * 33 + jj]      + prev[u][0];
            float fg = gbuf[b * 33 + 8 + jj]  + prev[u][1];
            float gg = gbuf[b * 33 + 16 + jj] + prev[u][2];
            float og = gbuf[b * 33 + 24 + jj] + prev[u][3];
            int j = j0 + jj;
            float c_old = g_c0[b * HDIM + j];
            float cn = sigf(fg) * c_old + sigf(ig) * tanhf(gg);
            float hv = sigf(og) * tanhf(cn);
            g_c0[b * HDIM + j] = cn;
            hn[b * HDIM + j]   = hv;
        }
        grid_bar(gen);   // h0(t) and h1(t-1) visible before layer 1

        // ======================= layer 1 =======================
        const float* h0t = g_h0[(t + 1) & 1];
        const float* h1p = g_h1[t & 1];
        float*       h1n = g_h1[(t + 1) & 1];

        float C2[2][4] = {};
        gemm3tf32(C2, h0t, Wih1, h1p, Whh1, 64, 32, j0, tid,
                  sAhi, sAlo, sBhi, sBlo);

        #pragma unroll
        for (int s = 0; s < 2; s++) {
            int col = cbase + s * 8 + 2 * tg;
            gbuf[mrow * 33 + col]           = C2[s][0];
            gbuf[mrow * 33 + col + 1]       = C2[s][1];
            gbuf[(mrow + 8) * 33 + col]     = C2[s][2];
            gbuf[(mrow + 8) * 33 + col + 1] = C2[s][3];
        }
        __syncthreads();

        #pragma unroll
        for (int u = 0; u < 2; u++) {
            int cell = tid * 2 + u;
            int b  = cell >> 3;
            int jj = cell & 7;
            float ig = gbuf[b * 33 + jj]      + bsum[u][0];
            float fg = gbuf[b * 33 + 8 + jj]  + bsum[u][1];
            float gg = gbuf[b * 33 + 16 + jj] + bsum[u][2];
            float og = gbuf[b * 33 + 24 + jj] + bsum[u][3];
            int j = j0 + jj;
            float c_old = g_c1[b * HDIM + j];
            float cn = sigf(fg) * c_old + sigf(ig) * tanhf(gg);
            float hv = sigf(og) * tanhf(cn);
            g_c1[b * HDIM + j] = cn;
            h1n[b * HDIM + j]  = hv;
            out[((size_t)b * TLEN + t) * HDIM + j] = hv;   // out[b, t, j]
        }
        __syncthreads();   // gbuf safe before next step's epilogue writes
    }

    // ---- pack final states (own slice; T even -> buffers [0]) ----
    const size_t BH   = (size_t)BSZ * HDIM;
    const size_t base = (size_t)BSZ * TLEN * HDIM;
    for (int u = tid; u < 64 * 8; u += 256) {
        int b = u >> 3, jj = u & 7;
        int idx = b * HDIM + j0 + jj;
        out[base + idx]          = g_h0[0][idx];
        out[base + BH + idx]     = g_h1[0][idx];
        out[base + 2 * BH + idx] = g_c0[idx];
        out[base + 3 * BH + idx] = g_c1[idx];
    }
}

// ---------------------------------------------------------------------------
// Launch: 2 kernel nodes only (graph-capturable, no upload-pool leak)
// ---------------------------------------------------------------------------
extern "C" void kernel_launch(void* const* d_in, const int* in_sizes, int n_in,
                              void* d_out, int out_size)
{
    (void)in_sizes; (void)n_in; (void)out_size;
    const float* x    = (const float*)d_in[0];
    const float* Wih0 = (const float*)d_in[1];
    const float* Whh0 = (const float*)d_in[2];
    const float* bih0 = (const float*)d_in[3];
    const float* bhh0 = (const float*)d_in[4];
    const float* Wih1 = (const float*)d_in[5];
    const float* Whh1 = (const float*)d_in[6];
    const float* bih1 = (const float*)d_in[7];
    const float* bhh1 = (const float*)d_in[8];
    float* out = (float*)d_out;

    dim3 pre_grid(G4H / 64, (BSZ * TLEN) / 64);
    pre_gemm_kernel<<<pre_grid, 256>>>(x, Wih0, bih0, bhh0);

    lstm_persistent_kernel<<<NCTA, 256>>>(Whh0, Wih1, Whh1, bih1, bhh1, out);
}

// round 11
// speedup vs baseline: 2.5203x; 1.3736x over previous
#include <cuda_runtime.h>
#include <math.h>
#include <stdint.h>

// Problem constants
#define BSZ  64
#define TLEN 512
#define FDIM 512
#define HDIM 1024
#define G4H  4096
#define NCTA 128    // persistent grid (<=148 SMs, all co-resident)

// ---------------------------------------------------------------------------
// Device-global scratch
// ---------------------------------------------------------------------------
__device__ float g_pre0[(size_t)TLEN * BSZ * G4H];          // [t][b][4H]

// h state, tf32 hi/lo, MMA-fragment order (see afrag_idx). Double-buffered.
__device__ float g_h0hi[2][BSZ * HDIM], g_h0lo[2][BSZ * HDIM];
__device__ float g_h1hi[2][BSZ * HDIM], g_h1lo[2][BSZ * HDIM];
// exact h (final-state pack only; overwritten every step)
__device__ float g_h0e[BSZ * HDIM], g_h1e[BSZ * HDIM];
__device__ float g_c0[BSZ * HDIM], g_c1[BSZ * HDIM];

// Weights, tf32 hi/lo, fragment order: [jb][chunk32][q][ntile][lane][reg2]
__device__ float g_w0hi[G4H * HDIM],  g_w0lo[G4H * HDIM];
__device__ float g_w1ihi[G4H * HDIM], g_w1ilo[G4H * HDIM];
__device__ float g_w1hhi[G4H * HDIM], g_w1hlo[G4H * HDIM];

// Grid barrier (monotone generation counter: survives graph replays)
__device__ unsigned g_bar_count = 0;
__device__ unsigned g_bar_gen   = 0;

// ---------------------------------------------------------------------------
// Software grid barrier
// ---------------------------------------------------------------------------
__device__ __forceinline__ void grid_bar(unsigned& gen) {
    __syncthreads();
    if (threadIdx.x == 0) {
        __threadfence();
        unsigned t = atomicAdd(&g_bar_count, 1u);
        if (t == NCTA - 1) {
            atomicExch(&g_bar_count, 0u);
            __threadfence();
            atomicAdd(&g_bar_gen, 1u);
        } else {
            while (atomicAdd(&g_bar_gen, 0u) <= gen) __nanosleep(40);
        }
        __threadfence();
    }
    gen++;
    __syncthreads();
}

// ---------------------------------------------------------------------------
// tf32 + cp.async helpers
// ---------------------------------------------------------------------------
__device__ __forceinline__ uint32_t f2tf32(float x) {
    uint32_t r;
    asm("cvt.rna.tf32.f32 %0, %1;" : "=r"(r) : "f"(x));
    return r;
}
__device__ __forceinline__ void cpa16(uint32_t s, const void* g) {
    asm volatile("cp.async.cg.shared.global [%0], [%1], 16;" :: "r"(s), "l"(g));
}
__device__ __forceinline__ void cp_commit() {
    asm volatile("cp.async.commit_group;");
}
template<int N> __device__ __forceinline__ void cp_wait() {
    asm volatile("cp.async.wait_group %0;" :: "n"(N));
}
__device__ __forceinline__ void mma8(float c[4],
    uint32_t a0, uint32_t a1, uint32_t a2, uint32_t a3,
    uint32_t b0, uint32_t b1)
{
    asm volatile(
        "mma.sync.aligned.m16n8k8.row.col.f32.tf32.tf32.f32 "
        "{%0,%1,%2,%3}, {%4,%5,%6,%7}, {%8,%9}, {%0,%1,%2,%3};"
        : "+f"(c[0]), "+f"(c[1]), "+f"(c[2]), "+f"(c[3])
        : "r"(a0), "r"(a1), "r"(a2), "r"(a3), "r"(b0), "r"(b1));
}

// A-fragment global index for element (m=batch row, k=hidden index).
// Layout: [chunk32 c][q][mg][lane][reg4]; per m16k8 tile:
//   lane = (rr&7)*4 + (kq&3), reg = (rr>>3) + 2*(kq>>2)   (rr=m&15, kq=k&7)
__device__ __forceinline__ int afrag_idx(int m, int k) {
    int c = k >> 5, q = (k >> 3) & 3, kq = k & 7;
    int mg = m >> 4, rr = m & 15;
    int lane = (rr & 7) * 4 + (kq & 3);
    int r = (rr >> 3) + ((kq >> 2) << 1);
    return (((c * 4 + q) * 4 + mg) * 32 + lane) * 4 + r;
}

// ---------------------------------------------------------------------------
// One-time (per launch) weight prep: tf32 hi/lo split into fragment order.
// e decodes: r(1b) | ln(5b) | nt(2b) | q(2b) | c(5b) | jb(7b)
// B frag (m16n8k8 col): lane = n*4 + (kq&3), reg = kq>>2.
// weight row = nt*HDIM + jb*8 + (ln>>2); k = c*32 + q*8 + (ln&3) + 4*r
// ---------------------------------------------------------------------------
__global__ __launch_bounds__(256) void wprep_kernel(const float* __restrict__ W, int which) {
    int e = blockIdx.x * blockDim.x + threadIdx.x;
    if (e >= G4H * HDIM) return;
    float* hi = (which == 0) ? g_w0hi : (which == 1) ? g_w1ihi : g_w1hhi;
    float* lo = (which == 0) ? g_w0lo : (which == 1) ? g_w1ilo : g_w1hlo;
    int r  = e & 1;
    int ln = (e >> 1) & 31;
    int nt = (e >> 6) & 3;
    int q  = (e >> 8) & 3;
    int c  = (e >> 10) & 31;
    int jb = e >> 15;
    int wrow = nt * HDIM + jb * 8 + (ln >> 2);
    int k    = c * 32 + q * 8 + (ln & 3) + 4 * r;
    float w  = W[(size_t)wrow * HDIM + k];
    float hf = __uint_as_float(f2tf32(w));
    hi[e] = hf;
    lo[e] = __uint_as_float(f2tf32(w - hf));
}

// ---------------------------------------------------------------------------
// pre_gemm v2: 128x128x16 tiles, 8x8 microtile, FFMA-bound.
// g_pre0[t][b][n] = x[b,t,:] @ W_ih_0[n,:] + b_ih_0[n] + b_hh_0[n]
// ---------------------------------------------------------------------------
#define PGP 132   // smem pitch (multiple of 4 for float4 align)

__global__ __launch_bounds__(256) void pre_gemm_kernel(
    const float* __restrict__ X,      // [B*T, F]
    const float* __restrict__ W,      // [4H, F]
    const float* __restrict__ bi,
    const float* __restrict__ bh)
{
    __shared__ float As[16 * PGP];
    __shared__ float Bs[16 * PGP];

    const int m0 = blockIdx.y * 128;
    const int n0 = blockIdx.x * 128;
    const int tid = threadIdx.x;
    const int ty = tid >> 4, tx = tid & 15;

    float acc[8][8] = {};

    for (int k0 = 0; k0 < FDIM; k0 += 16) {
        if (tid < 128) {
            const float* src = &X[(size_t)(m0 + tid) * FDIM + k0];
            #pragma unroll
            for (int i = 0; i < 16; i += 4) {
                float4 v = *(const float4*)(src + i);
                As[(i + 0) * PGP + tid] = v.x;
                As[(i + 1) * PGP + tid] = v.y;
                As[(i + 2) * PGP + tid] = v.z;
                As[(i + 3) * PGP + tid] = v.w;
            }
        } else {
            int rb = tid - 128;
            const float* src = &W[(size_t)(n0 + rb) * FDIM + k0];
            #pragma unroll
            for (int i = 0; i < 16; i += 4) {
                float4 v = *(const float4*)(src + i);
                Bs[(i + 0) * PGP + rb] = v.x;
                Bs[(i + 1) * PGP + rb] = v.y;
                Bs[(i + 2) * PGP + rb] = v.z;
                Bs[(i + 3) * PGP + rb] = v.w;
            }
        }
        __syncthreads();

        #pragma unroll
        for (int kk = 0; kk < 16; kk++) {
            float a[8], b[8];
            *(float4*)&a[0] = *(const float4*)&As[kk * PGP + ty * 8];
            *(float4*)&a[4] = *(const float4*)&As[kk * PGP + ty * 8 + 4];
            *(float4*)&b[0] = *(const float4*)&Bs[kk * PGP + tx * 8];
            *(float4*)&b[4] = *(const float4*)&Bs[kk * PGP + tx * 8 + 4];
            #pragma unroll
            for (int i = 0; i < 8; i++)
                #pragma unroll
                for (int j = 0; j < 8; j++)
                    acc[i][j] += a[i] * b[j];
        }
        __syncthreads();
    }

    float bsum[8];
    #pragma unroll
    for (int j = 0; j < 8; j++) {
        int n = n0 + tx * 8 + j;
        bsum[j] = bi[n] + bh[n];
    }
    #pragma unroll
    for (int i = 0; i < 8; i++) {
        int m = m0 + ty * 8 + i;
        int bb = m >> 9, t = m & 511;
        float* dst = &g_pre0[((size_t)t * BSZ + bb) * G4H + n0 + tx * 8];
        float4 v0, v1;
        v0.x = acc[i][0] + bsum[0]; v0.y = acc[i][1] + bsum[1];
        v0.z = acc[i][2] + bsum[2]; v0.w = acc[i][3] + bsum[3];
        v1.x = acc[i][4] + bsum[4]; v1.y = acc[i][5] + bsum[5];
        v1.z = acc[i][6] + bsum[6]; v1.w = acc[i][7] + bsum[7];
        *(float4*)dst = v0;
        *(float4*)(dst + 4) = v1;
    }
}

// ---------------------------------------------------------------------------
// Recurrent GEMM: fragment-ordered operands, cp.async 2-stage, K-chunk 64.
// Stage layout (floats): [Ahi 4096][Alo 4096][Bhi 2048][Blo 2048] = 12288
// ---------------------------------------------------------------------------
__device__ __forceinline__ void chunk_src(
    int p, int half64,
    const float* Ahi0, const float* Alo0, const float* Bhi0, const float* Blo0,
    const float* Ahi1, const float* Alo1, const float* Bhi1, const float* Blo1,
    const float*& ah, const float*& al, const float*& bh, const float*& bl)
{
    if (p < half64) {
        ah = Ahi0 + (size_t)p * 4096; al = Alo0 + (size_t)p * 4096;
        bh = Bhi0 + (size_t)p * 2048; bl = Blo0 + (size_t)p * 2048;
    } else {
        int q = p - half64;
        ah = Ahi1 + (size_t)q * 4096; al = Alo1 + (size_t)q * 4096;
        bh = Bhi1 + (size_t)q * 2048; bl = Blo1 + (size_t)q * 2048;
    }
}

__device__ __forceinline__ void stage_chunk(
    float* sm, int st, int tid,
    const float* ah, const float* al, const float* bh, const float* bl)
{
    uint32_t s = (uint32_t)__cvta_generic_to_shared(sm + st * 12288);
    #pragma unroll
    for (int i = 0; i < 4; i++)
        cpa16(s + (tid + i * 256) * 16, ah + (tid + i * 256) * 4);
    #pragma unroll
    for (int i = 0; i < 4; i++)
        cpa16(s + 16384 + (tid + i * 256) * 16, al + (tid + i * 256) * 4);
    #pragma unroll
    for (int i = 0; i < 2; i++)
        cpa16(s + 32768 + (tid + i * 256) * 16, bh + (tid + i * 256) * 4);
    #pragma unroll
    for (int i = 0; i < 2; i++)
        cpa16(s + 40960 + (tid + i * 256) * 16, bl + (tid + i * 256) * 4);
}

__device__ __forceinline__ void gemm_frag(
    float C[2][4],
    const float* Ahi0, const float* Alo0, const float* Bhi0, const float* Blo0,
    const float* Ahi1, const float* Alo1, const float* Bhi1, const float* Blo1,
    int n64, int half64, int tid, int mg, int ntbase, float* sm)
{
    const int ln = tid & 31;
    const float *ah, *al, *bh, *bl;

    chunk_src(0, half64, Ahi0, Alo0, Bhi0, Blo0, Ahi1, Alo1, Bhi1, Blo1, ah, al, bh, bl);
    stage_chunk(sm, 0, tid, ah, al, bh, bl);
    cp_commit();

    for (int p = 0; p < n64; p++) {
        if (p + 1 < n64) {
            chunk_src(p + 1, half64, Ahi0, Alo0, Bhi0, Blo0, Ahi1, Alo1, Bhi1, Blo1,
                      ah, al, bh, bl);
            stage_chunk(sm, (p + 1) & 1, tid, ah, al, bh, bl);
            cp_commit();
            cp_wait<1>();
        } else {
            cp_wait<0>();
        }
        __syncthreads();

        const float* sb = sm + (p & 1) * 12288;
        #pragma unroll
        for (int q8 = 0; q8 < 8; q8++) {
            int ch = q8 >> 2, qq = q8 & 3;
            int aoff = ch * 2048 + (qq * 4 + mg) * 128 + ln * 4;
            float4 fah = *(const float4*)(sb + aoff);
            float4 fal = *(const float4*)(sb + 4096 + aoff);
            uint32_t ah0 = __float_as_uint(fah.x), ah1 = __float_as_uint(fah.y);
            uint32_t ah2 = __float_as_uint(fah.z), ah3 = __float_as_uint(fah.w);
            uint32_t al0 = __float_as_uint(fal.x), al1 = __float_as_uint(fal.y);
            uint32_t al2 = __float_as_uint(fal.z), al3 = __float_as_uint(fal.w);
            #pragma unroll
            for (int s = 0; s < 2; s++) {
                int nt = ntbase + s;
                int boff = ch * 1024 + (qq * 4 + nt) * 64 + ln * 2;
                float2 fbh = *(const float2*)(sb + 8192 + boff);
                float2 fbl = *(const float2*)(sb + 10240 + boff);
                uint32_t bh0 = __float_as_uint(fbh.x), bh1 = __float_as_uint(fbh.y);
                uint32_t bl0 = __float_as_uint(fbl.x), bl1 = __float_as_uint(fbl.y);
                mma8(C[s], ah0, ah1, ah2, ah3, bh0, bh1);
                mma8(C[s], ah0, ah1, ah2, ah3, bl0, bl1);
                mma8(C[s], al0, al1, al2, al3, bh0, bh1);
            }
        }
        __syncthreads();
    }
}

__device__ __forceinline__ float sigf(float x) {
    return 1.f / (1.f + expf(-x));
}

// ---------------------------------------------------------------------------
// Persistent recurrence kernel
// ---------------------------------------------------------------------------
__global__ __launch_bounds__(256, 1) void lstm_persistent_kernel(
    const float* __restrict__ bi1, const float* __restrict__ bh1,
    float* __restrict__ out)
{
    extern __shared__ float sm[];          // 2*12288 stage + 2112 gbuf
    float* gbuf = sm + 24576;

    const int j0  = blockIdx.x * 8;
    const int tid = threadIdx.x;
    const int w   = tid >> 5;
    const int ln  = tid & 31;
    const int g   = ln >> 2;
    const int tg  = ln & 3;
    const int mg  = w & 3;
    const int ntbase = (w >> 2) * 2;
    const int mrow = mg * 16 + g;
    const int cbase = ntbase * 8;
    const size_t jbo = (size_t)blockIdx.x * 32768;   // weight frag per-jb offset

    unsigned gen = atomicAdd(&g_bar_gen, 0u);

    // ---- init own state slice (all b, j in [j0, j0+8)) ----
    for (int u = tid; u < 64 * 8; u += 256) {
        int b = u >> 3, jj = u & 7;
        int j = j0 + jj;
        int fi = afrag_idx(b, j);
        g_h0hi[0][fi] = 0.f; g_h0lo[0][fi] = 0.f;
        g_h1hi[0][fi] = 0.f; g_h1lo[0][fi] = 0.f;
        g_c0[b * HDIM + j] = 0.f;
        g_c1[b * HDIM + j] = 0.f;
    }
    grid_bar(gen);

    // ---- layer-1 bias sums ----
    float bsum[2][4];
    #pragma unroll
    for (int u = 0; u < 2; u++) {
        int jj = (tid * 2 + u) & 7;
        #pragma unroll
        for (int gt = 0; gt < 4; gt++)
            bsum[u][gt] = bi1[gt * HDIM + j0 + jj] + bh1[gt * HDIM + j0 + jj];
    }

    for (int t = 0; t < TLEN; t++) {
        // ======================= layer 0 =======================
        const float* Ah = g_h0hi[t & 1];
        const float* Al = g_h0lo[t & 1];

        float prev[2][4];
        {
            const float* pre = &g_pre0[(size_t)t * BSZ * G4H];
            #pragma unroll
            for (int u = 0; u < 2; u++) {
                int cell = tid * 2 + u;
                int b = cell >> 3, jj = cell & 7;
                #pragma unroll
                for (int gt = 0; gt < 4; gt++)
                    prev[u][gt] = pre[(size_t)b * G4H + gt * HDIM + j0 + jj];
            }
        }

        float C[2][4] = {};
        gemm_frag(C, Ah, Al, g_w0hi + jbo, g_w0lo + jbo,
                     Ah, Al, g_w0hi + jbo, g_w0lo + jbo,
                  16, 16, tid, mg, ntbase, sm);

        #pragma unroll
        for (int s = 0; s < 2; s++) {
            int col = cbase + s * 8 + 2 * tg;
            gbuf[mrow * 33 + col]           = C[s][0];
            gbuf[mrow * 33 + col + 1]       = C[s][1];
            gbuf[(mrow + 8) * 33 + col]     = C[s][2];
            gbuf[(mrow + 8) * 33 + col + 1] = C[s][3];
        }
        __syncthreads();

        #pragma unroll
        for (int u = 0; u < 2; u++) {
            int cell = tid * 2 + u;
            int b  = cell >> 3;
            int jj = cell & 7;
            float ig = gbuf[b * 33 + jj]      + prev[u][0];
            float fg = gbuf[b * 33 + 8 + jj]  + prev[u][1];
            float gg = gbuf[b * 33 + 16 + jj] + prev[u][2];
            float og = gbuf[b * 33 + 24 + jj] + prev[u][3];
            int j = j0 + jj;
            float c_old = g_c0[b * HDIM + j];
            float cn = sigf(fg) * c_old + sigf(ig) * tanhf(gg);
            float hv = sigf(og) * tanhf(cn);
            g_c0[b * HDIM + j] = cn;
            g_h0e[b * HDIM + j] = hv;
            float hif = __uint_as_float(f2tf32(hv));
            float lof = __uint_as_float(f2tf32(hv - hif));
            int fi = afrag_idx(b, j);
            g_h0hi[(t + 1) & 1][fi] = hif;
            g_h0lo[(t + 1) & 1][fi] = lof;
        }
        grid_bar(gen);   // h0(t) / h1(t-1) frags visible before layer 1

        // ======================= layer 1 =======================
        const float* A0h = g_h0hi[(t + 1) & 1];
        const float* A0l = g_h0lo[(t + 1) & 1];
        const float* A1h = g_h1hi[t & 1];
        const float* A1l = g_h1lo[t & 1];

        float C2[2][4] = {};
        gemm_frag(C2, A0h, A0l, g_w1ihi + jbo, g_w1ilo + jbo,
                      A1h, A1l, g_w1hhi + jbo, g_w1hlo + jbo,
                  32, 16, tid, mg, ntbase, sm);

        #pragma unroll
        for (int s = 0; s < 2; s++) {
            int col = cbase + s * 8 + 2 * tg;
            gbuf[mrow * 33 + col]           = C2[s][0];
            gbuf[mrow * 33 + col + 1]       = C2[s][1];
            gbuf[(mrow + 8) * 33 + col]     = C2[s][2];
            gbuf[(mrow + 8) * 33 + col + 1] = C2[s][3];
        }
        __syncthreads();

        #pragma unroll
        for (int u = 0; u < 2; u++) {
            int cell = tid * 2 + u;
            int b  = cell >> 3;
            int jj = cell & 7;
            float ig = gbuf[b * 33 + jj]      + bsum[u][0];
            float fg = gbuf[b * 33 + 8 + jj]  + bsum[u][1];
            float gg = gbuf[b * 33 + 16 + jj] + bsum[u][2];
            float og = gbuf[b * 33 + 24 + jj] + bsum[u][3];
            int j = j0 + jj;
            float c_old = g_c1[b * HDIM + j];
            float cn = sigf(fg) * c_old + sigf(ig) * tanhf(gg);
            float hv = sigf(og) * tanhf(cn);
            g_c1[b * HDIM + j] = cn;
            g_h1e[b * HDIM + j] = hv;
            out[((size_t)b * TLEN + t) * HDIM + j] = hv;
            float hif = __uint_as_float(f2tf32(hv));
            float lof = __uint_as_float(f2tf32(hv - hif));
            int fi = afrag_idx(b, j);
            g_h1hi[(t + 1) & 1][fi] = hif;
            g_h1lo[(t + 1) & 1][fi] = lof;
        }
        __syncthreads();   // gbuf reuse safety; cross-CTA ordered by next bar
    }

    // ---- pack final states ----
    const size_t BH   = (size_t)BSZ * HDIM;
    const size_t base = (size_t)BSZ * TLEN * HDIM;
    for (int u = tid; u < 64 * 8; u += 256) {
        int b = u >> 3, jj = u & 7;
        int idx = b * HDIM + j0 + jj;
        out[base + idx]          = g_h0e[idx];
        out[base + BH + idx]     = g_h1e[idx];
        out[base + 2 * BH + idx] = g_c0[idx];
        out[base + 3 * BH + idx] = g_c1[idx];
    }
}

// ---------------------------------------------------------------------------
// Launch (graph-capturable; few nodes)
// ---------------------------------------------------------------------------
extern "C" void kernel_launch(void* const* d_in, const int* in_sizes, int n_in,
                              void* d_out, int out_size)
{
    (void)in_sizes; (void)n_in; (void)out_size;
    const float* x    = (const float*)d_in[0];
    const float* Wih0 = (const float*)d_in[1];
    const float* Whh0 = (const float*)d_in[2];
    const float* bih0 = (const float*)d_in[3];
    const float* bhh0 = (const float*)d_in[4];
    const float* Wih1 = (const float*)d_in[5];
    const float* Whh1 = (const float*)d_in[6];
    const float* bih1 = (const float*)d_in[7];
    const float* bhh1 = (const float*)d_in[8];
    float* out = (float*)d_out;

    const int smem_bytes = (2 * 12288 + 2112) * 4;   // 106752
    cudaFuncSetAttribute(lstm_persistent_kernel,
                         cudaFuncAttributeMaxDynamicSharedMemorySize, smem_bytes);

    // per-launch weight prep (deterministic, re-done every call)
    const int WPN = (G4H * HDIM + 255) / 256;
    wprep_kernel<<<WPN, 256>>>(Whh0, 0);
    wprep_kernel<<<WPN, 256>>>(Wih1, 1);
    wprep_kernel<<<WPN, 256>>>(Whh1, 2);

    dim3 pre_grid(G4H / 128, (BSZ * TLEN) / 128);    // 32 x 256
    pre_gemm_kernel<<<pre_grid, 256>>>(x, Wih0, bih0, bhh0);

    lstm_persistent_kernel<<<NCTA, 256, smem_bytes>>>(bih1, bhh1, out);
}

// round 13
// speedup vs baseline: 2.5271x; 1.0027x over previous
#include <cuda_runtime.h>
#include <math.h>
#include <stdint.h>

// Problem constants
#define BSZ  64
#define TLEN 512
#define FDIM 512
#define HDIM 1024
#define G4H  4096
#define NCTA 128    // persistent grid (<=148 SMs, all co-resident)

// ---------------------------------------------------------------------------
// Device-global scratch
// ---------------------------------------------------------------------------
__device__ float g_pre0[(size_t)TLEN * BSZ * G4H];          // [t][b][4H]

// h state, tf32 hi/lo, MMA-fragment order (see afrag_idx). Double-buffered.
__device__ float g_h0hi[2][BSZ * HDIM], g_h0lo[2][BSZ * HDIM];
__device__ float g_h1hi[2][BSZ * HDIM], g_h1lo[2][BSZ * HDIM];
// exact h (final-state pack only; overwritten every step)
__device__ float g_h0e[BSZ * HDIM], g_h1e[BSZ * HDIM];
__device__ float g_c0[BSZ * HDIM], g_c1[BSZ * HDIM];

// Weights, tf32 hi/lo, fragment order: [jb][chunk32][q][ntile][lane][reg2]
__device__ float g_w0hi[G4H * HDIM],  g_w0lo[G4H * HDIM];
__device__ float g_w1ihi[G4H * HDIM], g_w1ilo[G4H * HDIM];
__device__ float g_w1hhi[G4H * HDIM], g_w1hlo[G4H * HDIM];

// Grid barrier (monotone generation counter: survives graph replays)
__device__ unsigned g_bar_count = 0;
__device__ unsigned g_bar_gen   = 0;

// ---------------------------------------------------------------------------
// Software grid barrier
// ---------------------------------------------------------------------------
__device__ __forceinline__ void grid_bar(unsigned& gen) {
    __syncthreads();
    if (threadIdx.x == 0) {
        __threadfence();
        unsigned t = atomicAdd(&g_bar_count, 1u);
        if (t == NCTA - 1) {
            atomicExch(&g_bar_count, 0u);
            __threadfence();
            atomicAdd(&g_bar_gen, 1u);
        } else {
            while (atomicAdd(&g_bar_gen, 0u) <= gen) __nanosleep(40);
        }
        __threadfence();
    }
    gen++;
    __syncthreads();
}

// ---------------------------------------------------------------------------
// tf32 + cp.async helpers
// ---------------------------------------------------------------------------
__device__ __forceinline__ uint32_t f2tf32(float x) {
    uint32_t r;
    asm("cvt.rna.tf32.f32 %0, %1;" : "=r"(r) : "f"(x));
    return r;
}
__device__ __forceinline__ void cpa16(uint32_t s, const void* g) {
    asm volatile("cp.async.cg.shared.global [%0], [%1], 16;" :: "r"(s), "l"(g));
}
__device__ __forceinline__ void cp_commit() {
    asm volatile("cp.async.commit_group;");
}
template<int N> __device__ __forceinline__ void cp_wait() {
    asm volatile("cp.async.wait_group %0;" :: "n"(N));
}
__device__ __forceinline__ void mma8(float c[4],
    uint32_t a0, uint32_t a1, uint32_t a2, uint32_t a3,
    uint32_t b0, uint32_t b1)
{
    asm volatile(
        "mma.sync.aligned.m16n8k8.row.col.f32.tf32.tf32.f32 "
        "{%0,%1,%2,%3}, {%4,%5,%6,%7}, {%8,%9}, {%0,%1,%2,%3};"
        : "+f"(c[0]), "+f"(c[1]), "+f"(c[2]), "+f"(c[3])
        : "r"(a0), "r"(a1), "r"(a2), "r"(a3), "r"(b0), "r"(b1));
}

// A-fragment global index for element (m=batch row, k=hidden index).
// Layout: [chunk32 c][q][mg][lane][reg4]; per m16k8 tile:
//   lane = (rr&7)*4 + (kq&3), reg = (rr>>3) + 2*(kq>>2)   (rr=m&15, kq=k&7)
__device__ __forceinline__ int afrag_idx(int m, int k) {
    int c = k >> 5, q = (k >> 3) & 3, kq = k & 7;
    int mg = m >> 4, rr = m & 15;
    int lane = (rr & 7) * 4 + (kq & 3);
    int r = (rr >> 3) + ((kq >> 2) << 1);
    return (((c * 4 + q) * 4 + mg) * 32 + lane) * 4 + r;
}

// ---------------------------------------------------------------------------
// One-time (per launch) weight prep: tf32 hi/lo split into fragment order.
// e decodes: r(1b) | ln(5b) | nt(2b) | q(2b) | c(5b) | jb(7b)
// B frag (m16n8k8 col): lane = n*4 + (kq&3), reg = kq>>2.
// weight row = nt*HDIM + jb*8 + (ln>>2); k = c*32 + q*8 + (ln&3) + 4*r
// ---------------------------------------------------------------------------
__global__ __launch_bounds__(256) void wprep_kernel(const float* __restrict__ W, int which) {
    int e = blockIdx.x * blockDim.x + threadIdx.x;
    if (e >= G4H * HDIM) return;
    float* hi = (which == 0) ? g_w0hi : (which == 1) ? g_w1ihi : g_w1hhi;
    float* lo = (which == 0) ? g_w0lo : (which == 1) ? g_w1ilo : g_w1hlo;
    int r  = e & 1;
    int ln = (e >> 1) & 31;
    int nt = (e >> 6) & 3;
    int q  = (e >> 8) & 3;
    int c  = (e >> 10) & 31;
    int jb = e >> 15;
    int wrow = nt * HDIM + jb * 8 + (ln >> 2);
    int k    = c * 32 + q * 8 + (ln & 3) + 4 * r;
    float w  = W[(size_t)wrow * HDIM + k];
    float hf = __uint_as_float(f2tf32(w));
    hi[e] = hf;
    lo[e] = __uint_as_float(f2tf32(w - hf));
}

// ---------------------------------------------------------------------------
// pre_gemm v2: 128x128x16 tiles, 8x8 microtile, FFMA-bound.
// g_pre0[t][b][n] = x[b,t,:] @ W_ih_0[n,:] + b_ih_0[n] + b_hh_0[n]
// ---------------------------------------------------------------------------
#define PGP 132   // smem pitch (multiple of 4 for float4 align)

__global__ __launch_bounds__(256) void pre_gemm_kernel(
    const float* __restrict__ X,      // [B*T, F]
    const float* __restrict__ W,      // [4H, F]
    const float* __restrict__ bi,
    const float* __restrict__ bh)
{
    __shared__ float As[16 * PGP];
    __shared__ float Bs[16 * PGP];

    const int m0 = blockIdx.y * 128;
    const int n0 = blockIdx.x * 128;
    const int tid = threadIdx.x;
    const int ty = tid >> 4, tx = tid & 15;

    float acc[8][8] = {};

    for (int k0 = 0; k0 < FDIM; k0 += 16) {
        if (tid < 128) {
            const float* src = &X[(size_t)(m0 + tid) * FDIM + k0];
            #pragma unroll
            for (int i = 0; i < 16; i += 4) {
                float4 v = *(const float4*)(src + i);
                As[(i + 0) * PGP + tid] = v.x;
                As[(i + 1) * PGP + tid] = v.y;
                As[(i + 2) * PGP + tid] = v.z;
                As[(i + 3) * PGP + tid] = v.w;
            }
        } else {
            int rb = tid - 128;
            const float* src = &W[(size_t)(n0 + rb) * FDIM + k0];
            #pragma unroll
            for (int i = 0; i < 16; i += 4) {
                float4 v = *(const float4*)(src + i);
                Bs[(i + 0) * PGP + rb] = v.x;
                Bs[(i + 1) * PGP + rb] = v.y;
                Bs[(i + 2) * PGP + rb] = v.z;
                Bs[(i + 3) * PGP + rb] = v.w;
            }
        }
        __syncthreads();

        #pragma unroll
        for (int kk = 0; kk < 16; kk++) {
            float a[8], b[8];
            *(float4*)&a[0] = *(const float4*)&As[kk * PGP + ty * 8];
            *(float4*)&a[4] = *(const float4*)&As[kk * PGP + ty * 8 + 4];
            *(float4*)&b[0] = *(const float4*)&Bs[kk * PGP + tx * 8];
            *(float4*)&b[4] = *(const float4*)&Bs[kk * PGP + tx * 8 + 4];
            #pragma unroll
            for (int i = 0; i < 8; i++)
                #pragma unroll
                for (int j = 0; j < 8; j++)
                    acc[i][j] += a[i] * b[j];
        }
        __syncthreads();
    }

    float bsum[8];
    #pragma unroll
    for (int j = 0; j < 8; j++) {
        int n = n0 + tx * 8 + j;
        bsum[j] = bi[n] + bh[n];
    }
    #pragma unroll
    for (int i = 0; i < 8; i++) {
        int m = m0 + ty * 8 + i;
        int bb = m >> 9, t = m & 511;
        float* dst = &g_pre0[((size_t)t * BSZ + bb) * G4H + n0 + tx * 8];
        float4 v0, v1;
        v0.x = acc[i][0] + bsum[0]; v0.y = acc[i][1] + bsum[1];
        v0.z = acc[i][2] + bsum[2]; v0.w = acc[i][3] + bsum[3];
        v1.x = acc[i][4] + bsum[4]; v1.y = acc[i][5] + bsum[5];
        v1.z = acc[i][6] + bsum[6]; v1.w = acc[i][7] + bsum[7];
        *(float4*)dst = v0;
        *(float4*)(dst + 4) = v1;
    }
}

// ---------------------------------------------------------------------------
// Recurrent GEMM: fragment-ordered operands, cp.async 2-stage, K-chunk 64.
// Stage layout (floats): [Ahi 4096][Alo 4096][Bhi 2048][Blo 2048] = 12288
// ---------------------------------------------------------------------------
__device__ __forceinline__ void chunk_src(
    int p, int half64,
    const float* Ahi0, const float* Alo0, const float* Bhi0, const float* Blo0,
    const float* Ahi1, const float* Alo1, const float* Bhi1, const float* Blo1,
    const float*& ah, const float*& al, const float*& bh, const float*& bl)
{
    if (p < half64) {
        ah = Ahi0 + (size_t)p * 4096; al = Alo0 + (size_t)p * 4096;
        bh = Bhi0 + (size_t)p * 2048; bl = Blo0 + (size_t)p * 2048;
    } else {
        int q = p - half64;
        ah = Ahi1 + (size_t)q * 4096; al = Alo1 + (size_t)q * 4096;
        bh = Bhi1 + (size_t)q * 2048; bl = Blo1 + (size_t)q * 2048;
    }
}

__device__ __forceinline__ void stage_chunk(
    float* sm, int st, int tid,
    const float* ah, const float* al, const float* bh, const float* bl)
{
    uint32_t s = (uint32_t)__cvta_generic_to_shared(sm + st * 12288);
    #pragma unroll
    for (int i = 0; i < 4; i++)
        cpa16(s + (tid + i * 256) * 16, ah + (tid + i * 256) * 4);
    #pragma unroll
    for (int i = 0; i < 4; i++)
        cpa16(s + 16384 + (tid + i * 256) * 16, al + (tid + i * 256) * 4);
    #pragma unroll
    for (int i = 0; i < 2; i++)
        cpa16(s + 32768 + (tid + i * 256) * 16, bh + (tid + i * 256) * 4);
    #pragma unroll
    for (int i = 0; i < 2; i++)
        cpa16(s + 40960 + (tid + i * 256) * 16, bl + (tid + i * 256) * 4);
}

__device__ __forceinline__ void gemm_frag(
    float C[2][4],
    const float* Ahi0, const float* Alo0, const float* Bhi0, const float* Blo0,
    const float* Ahi1, const float* Alo1, const float* Bhi1, const float* Blo1,
    int n64, int half64, int tid, int mg, int ntbase, float* sm)
{
    const int ln = tid & 31;
    const float *ah, *al, *bh, *bl;

    chunk_src(0, half64, Ahi0, Alo0, Bhi0, Blo0, Ahi1, Alo1, Bhi1, Blo1, ah, al, bh, bl);
    stage_chunk(sm, 0, tid, ah, al, bh, bl);
    cp_commit();

    for (int p = 0; p < n64; p++) {
        if (p + 1 < n64) {
            chunk_src(p + 1, half64, Ahi0, Alo0, Bhi0, Blo0, Ahi1, Alo1, Bhi1, Blo1,
                      ah, al, bh, bl);
            stage_chunk(sm, (p + 1) & 1, tid, ah, al, bh, bl);
            cp_commit();
            cp_wait<1>();
        } else {
            cp_wait<0>();
        }
        __syncthreads();

        const float* sb = sm + (p & 1) * 12288;
        #pragma unroll
        for (int q8 = 0; q8 < 8; q8++) {
            int ch = q8 >> 2, qq = q8 & 3;
            int aoff = ch * 2048 + (qq * 4 + mg) * 128 + ln * 4;
            float4 fah = *(const float4*)(sb + aoff);
            float4 fal = *(const float4*)(sb + 4096 + aoff);
            uint32_t ah0 = __float_as_uint(fah.x), ah1 = __float_as_uint(fah.y);
            uint32_t ah2 = __float_as_uint(fah.z), ah3 = __float_as_uint(fah.w);
            uint32_t al0 = __float_as_uint(fal.x), al1 = __float_as_uint(fal.y);
            uint32_t al2 = __float_as_uint(fal.z), al3 = __float_as_uint(fal.w);
            #pragma unroll
            for (int s = 0; s < 2; s++) {
                int nt = ntbase + s;
                int boff = ch * 1024 + (qq * 4 + nt) * 64 + ln * 2;
                float2 fbh = *(const float2*)(sb + 8192 + boff);
                float2 fbl = *(const float2*)(sb + 10240 + boff);
                uint32_t bh0 = __float_as_uint(fbh.x), bh1 = __float_as_uint(fbh.y);
                uint32_t bl0 = __float_as_uint(fbl.x), bl1 = __float_as_uint(fbl.y);
                mma8(C[s], ah0, ah1, ah2, ah3, bh0, bh1);
                mma8(C[s], ah0, ah1, ah2, ah3, bl0, bl1);
                mma8(C[s], al0, al1, al2, al3, bh0, bh1);
            }
        }
        __syncthreads();
    }
}

__device__ __forceinline__ float sigf(float x) {
    return 1.f / (1.f + expf(-x));
}

// ---------------------------------------------------------------------------
// Persistent recurrence kernel
// ---------------------------------------------------------------------------
__global__ __launch_bounds__(256, 1) void lstm_persistent_kernel(
    const float* __restrict__ bi1, const float* __restrict__ bh1,
    float* __restrict__ out)
{
    extern __shared__ float sm[];          // 2*12288 stage + 2112 gbuf
    float* gbuf = sm + 24576;

    const int j0  = blockIdx.x * 8;
    const int tid = threadIdx.x;
    const int w   = tid >> 5;
    const int ln  = tid & 31;
    const int g   = ln >> 2;
    const int tg  = ln & 3;
    const int mg  = w & 3;
    const int ntbase = (w >> 2) * 2;
    const int mrow = mg * 16 + g;
    const int cbase = ntbase * 8;
    const size_t jbo = (size_t)blockIdx.x * 32768;   // weight frag per-jb offset

    unsigned gen = atomicAdd(&g_bar_gen, 0u);

    // ---- init own state slice (all b, j in [j0, j0+8)) ----
    for (int u = tid; u < 64 * 8; u += 256) {
        int b = u >> 3, jj = u & 7;
        int j = j0 + jj;
        int fi = afrag_idx(b, j);
        g_h0hi[0][fi] = 0.f; g_h0lo[0][fi] = 0.f;
        g_h1hi[0][fi] = 0.f; g_h1lo[0][fi] = 0.f;
        g_c0[b * HDIM + j] = 0.f;
        g_c1[b * HDIM + j] = 0.f;
    }
    grid_bar(gen);

    // ---- layer-1 bias sums ----
    float bsum[2][4];
    #pragma unroll
    for (int u = 0; u < 2; u++) {
        int jj = (tid * 2 + u) & 7;
        #pragma unroll
        for (int gt = 0; gt < 4; gt++)
            bsum[u][gt] = bi1[gt * HDIM + j0 + jj] + bh1[gt * HDIM + j0 + jj];
    }

    for (int t = 0; t < TLEN; t++) {
        // ======================= layer 0 =======================
        const float* Ah = g_h0hi[t & 1];
        const float* Al = g_h0lo[t & 1];

        float prev[2][4];
        {
            const float* pre = &g_pre0[(size_t)t * BSZ * G4H];
            #pragma unroll
            for (int u = 0; u < 2; u++) {
                int cell = tid * 2 + u;
                int b = cell >> 3, jj = cell & 7;
                #pragma unroll
                for (int gt = 0; gt < 4; gt++)
                    prev[u][gt] = pre[(size_t)b * G4H + gt * HDIM + j0 + jj];
            }
        }

        float C[2][4] = {};
        gemm_frag(C, Ah, Al, g_w0hi + jbo, g_w0lo + jbo,
                     Ah, Al, g_w0hi + jbo, g_w0lo + jbo,
                  16, 16, tid, mg, ntbase, sm);

        #pragma unroll
        for (int s = 0; s < 2; s++) {
            int col = cbase + s * 8 + 2 * tg;
            gbuf[mrow * 33 + col]           = C[s][0];
            gbuf[mrow * 33 + col + 1]       = C[s][1];
            gbuf[(mrow + 8) * 33 + col]     = C[s][2];
            gbuf[(mrow + 8) * 33 + col + 1] = C[s][3];
        }
        __syncthreads();

        #pragma unroll
        for (int u = 0; u < 2; u++) {
            int cell = tid * 2 + u;
            int b  = cell >> 3;
            int jj = cell & 7;
            float ig = gbuf[b * 33 + jj]      + prev[u][0];
            float fg = gbuf[b * 33 + 8 + jj]  + prev[u][1];
            float gg = gbuf[b * 33 + 16 + jj] + prev[u][2];
            float og = gbuf[b * 33 + 24 + jj] + prev[u][3];
            int j = j0 + jj;
            float c_old = g_c0[b * HDIM + j];
            float cn = sigf(fg) * c_old + sigf(ig) * tanhf(gg);
            float hv = sigf(og) * tanhf(cn);
            g_c0[b * HDIM + j] = cn;
            g_h0e[b * HDIM + j] = hv;
            float hif = __uint_as_float(f2tf32(hv));
            float lof = __uint_as_float(f2tf32(hv - hif));
            int fi = afrag_idx(b, j);
            g_h0hi[(t + 1) & 1][fi] = hif;
            g_h0lo[(t + 1) & 1][fi] = lof;
        }
        grid_bar(gen);   // h0(t) / h1(t-1) frags visible before layer 1

        // ======================= layer 1 =======================
        const float* A0h = g_h0hi[(t + 1) & 1];
        const float* A0l = g_h0lo[(t + 1) & 1];
        const float* A1h = g_h1hi[t & 1];
        const float* A1l = g_h1lo[t & 1];

        float C2[2][4] = {};
        gemm_frag(C2, A0h, A0l, g_w1ihi + jbo, g_w1ilo + jbo,
                      A1h, A1l, g_w1hhi + jbo, g_w1hlo + jbo,
                  32, 16, tid, mg, ntbase, sm);

        #pragma unroll
        for (int s = 0; s < 2; s++) {
            int col = cbase + s * 8 + 2 * tg;
            gbuf[mrow * 33 + col]           = C2[s][0];
            gbuf[mrow * 33 + col + 1]       = C2[s][1];
            gbuf[(mrow + 8) * 33 + col]     = C2[s][2];
            gbuf[(mrow + 8) * 33 + col + 1] = C2[s][3];
        }
        __syncthreads();

        #pragma unroll
        for (int u = 0; u < 2; u++) {
            int cell = tid * 2 + u;
            int b  = cell >> 3;
            int jj = cell & 7;
            float ig = gbuf[b * 33 + jj]      + bsum[u][0];
            float fg = gbuf[b * 33 + 8 + jj]  + bsum[u][1];
            float gg = gbuf[b * 33 + 16 + jj] + bsum[u][2];
            float og = gbuf[b * 33 + 24 + jj] + bsum[u][3];
            int j = j0 + jj;
            float c_old = g_c1[b * HDIM + j];
            float cn = sigf(fg) * c_old + sigf(ig) * tanhf(gg);
            float hv = sigf(og) * tanhf(cn);
            g_c1[b * HDIM + j] = cn;
            g_h1e[b * HDIM + j] = hv;
            out[((size_t)b * TLEN + t) * HDIM + j] = hv;
            float hif = __uint_as_float(f2tf32(hv));
            float lof = __uint_as_float(f2tf32(hv - hif));
            int fi = afrag_idx(b, j);
            g_h1hi[(t + 1) & 1][fi] = hif;
            g_h1lo[(t + 1) & 1][fi] = lof;
        }
        __syncthreads();   // gbuf reuse safety; cross-CTA ordered by next bar
    }

    // ---- pack final states ----
    const size_t BH   = (size_t)BSZ * HDIM;
    const size_t base = (size_t)BSZ * TLEN * HDIM;
    for (int u = tid; u < 64 * 8; u += 256) {
        int b = u >> 3, jj = u & 7;
        int idx = b * HDIM + j0 + jj;
        out[base + idx]          = g_h0e[idx];
        out[base + BH + idx]     = g_h1e[idx];
        out[base + 2 * BH + idx] = g_c0[idx];
        out[base + 3 * BH + idx] = g_c1[idx];
    }
}

// ---------------------------------------------------------------------------
// Launch (graph-capturable; few nodes)
// ---------------------------------------------------------------------------
extern "C" void kernel_launch(void* const* d_in, const int* in_sizes, int n_in,
                              void* d_out, int out_size)
{
    (void)in_sizes; (void)n_in; (void)out_size;
    const float* x    = (const float*)d_in[0];
    const float* Wih0 = (const float*)d_in[1];
    const float* Whh0 = (const float*)d_in[2];
    const float* bih0 = (const float*)d_in[3];
    const float* bhh0 = (const float*)d_in[4];
    const float* Wih1 = (const float*)d_in[5];
    const float* Whh1 = (const float*)d_in[6];
    const float* bih1 = (const float*)d_in[7];
    const float* bhh1 = (const float*)d_in[8];
    float* out = (float*)d_out;

    const int smem_bytes = (2 * 12288 + 2112) * 4;   // 106752
    cudaFuncSetAttribute(lstm_persistent_kernel,
                         cudaFuncAttributeMaxDynamicSharedMemorySize, smem_bytes);

    // per-launch weight prep (deterministic, re-done every call)
    const int WPN = (G4H * HDIM + 255) / 256;
    wprep_kernel<<<WPN, 256>>>(Whh0, 0);
    wprep_kernel<<<WPN, 256>>>(Wih1, 1);
    wprep_kernel<<<WPN, 256>>>(Whh1, 2);

    dim3 pre_grid(G4H / 128, (BSZ * TLEN) / 128);    // 32 x 256
    pre_gemm_kernel<<<pre_grid, 256>>>(x, Wih0, bih0, bhh0);

    lstm_persistent_kernel<<<NCTA, 256, smem_bytes>>>(bih1, bhh1, out);
}

// round 16
// speedup vs baseline: 3.9012x; 1.5438x over previous
#include <cuda_runtime.h>
#include <cuda_fp16.h>
#include <math.h>
#include <stdint.h>

// Problem constants
#define BSZ  64
#define TLEN 512
#define FDIM 512
#define HDIM 1024
#define G4H  4096
#define NCTA 128    // persistent grid (<=148 SMs, all co-resident)

#define LOSCALE 4096.0f      // lo parts stored x2^12 (keeps fp16 normal)
#define LOINV   (1.0f/4096.0f)

// ---------------------------------------------------------------------------
// Device-global scratch
// ---------------------------------------------------------------------------
__device__ float g_pre0[(size_t)TLEN * BSZ * G4H];          // [t][b][4H]

// h state: fp16 hi / scaled-lo, packed half2, MMA A-fragment order
// (see afrag_u32). 16 chunks x 2048 uint32 = 32768 per buffer. Double-buffered.
__device__ uint32_t g_h0hi[2][32768], g_h0lo[2][32768];
__device__ uint32_t g_h1hi[2][32768], g_h1lo[2][32768];
// exact h/c (final-state pack)
__device__ float g_h0e[BSZ * HDIM], g_h1e[BSZ * HDIM];
__device__ float g_c0[BSZ * HDIM],  g_c1[BSZ * HDIM];

// Weights fp16 hi / scaled-lo, packed half2, MMA B-fragment order:
// [jb 0..127][chunk 0..15][q 0..3][nt 0..3][lane 0..31][reg 0..1]
// = 128 * 16384 uint32 per matrix
__device__ uint32_t g_w0hi[2097152],  g_w0lo[2097152];
__device__ uint32_t g_w1ihi[2097152], g_w1ilo[2097152];
__device__ uint32_t g_w1hhi[2097152], g_w1hlo[2097152];

// Grid barrier (monotone generation counter: survives graph replays)
__device__ unsigned g_bar_count = 0;
__device__ unsigned g_bar_gen   = 0;

// ---------------------------------------------------------------------------
// Software grid barrier
// ---------------------------------------------------------------------------
__device__ __forceinline__ void grid_bar(unsigned& gen) {
    __syncthreads();
    if (threadIdx.x == 0) {
        __threadfence();
        unsigned t = atomicAdd(&g_bar_count, 1u);
        if (t == NCTA - 1) {
            atomicExch(&g_bar_count, 0u);
            __threadfence();
            atomicAdd(&g_bar_gen, 1u);
        } else {
            while (atomicAdd(&g_bar_gen, 0u) <= gen) __nanosleep(40);
        }
        __threadfence();
    }
    gen++;
    __syncthreads();
}

// ---------------------------------------------------------------------------
// helpers
// ---------------------------------------------------------------------------
__device__ __forceinline__ void cpa16(uint32_t s, const void* g) {
    asm volatile("cp.async.cg.shared.global [%0], [%1], 16;" :: "r"(s), "l"(g));
}
__device__ __forceinline__ void cp_commit() {
    asm volatile("cp.async.commit_group;");
}
template<int N> __device__ __forceinline__ void cp_wait() {
    asm volatile("cp.async.wait_group %0;" :: "n"(N));
}

// fp16 m16n8k16: D(f32) += A(f16,row) * B(f16,col)
__device__ __forceinline__ void mma16(float c[4], uint4 a, uint2 b) {
    asm volatile(
        "mma.sync.aligned.m16n8k16.row.col.f32.f16.f16.f32 "
        "{%0,%1,%2,%3}, {%4,%5,%6,%7}, {%8,%9}, {%0,%1,%2,%3};"
        : "+f"(c[0]), "+f"(c[1]), "+f"(c[2]), "+f"(c[3])
        : "r"(a.x), "r"(a.y), "r"(a.z), "r"(a.w), "r"(b.x), "r"(b.y));
}

// A-fragment uint32 index for (m = batch row, k = hidden index).
// PTX m16n8k16 f16 A map: lane = (m&7)*4 + ((k&15)>>1 & 3),
// reg = ((m&15)>>3) + 2*((k&15)>>3), low half = even k.
__device__ __forceinline__ int afrag_u32(int m, int k) {
    int c = k >> 6, q = (k >> 4) & 3, kq = k & 15;
    int mg = m >> 4, rr = m & 15;
    int lane = (rr & 7) * 4 + ((kq >> 1) & 3);
    int reg  = (rr >> 3) + ((kq >> 3) << 1);
    return (((c * 4 + q) * 4 + mg) * 32 + lane) * 4 + reg;
}

__device__ __forceinline__ uint32_t packh2(float x0, float x1) {
    __half2 h = __halves2half2(__float2half_rn(x0), __float2half_rn(x1));
    return *(uint32_t*)&h;
}
__device__ __forceinline__ float sigf(float x) { return 1.f / (1.f + expf(-x)); }

// ---------------------------------------------------------------------------
// Weight prep: fp16 hi + scaled-lo into B-fragment order (packed half2).
// e (uint32 index) decodes: reg(1b)|lane(5b)|nt(2b)|q(2b)|c(4b)|jb(7b).
// PTX B map (k16n8 col): lane = n*4 + ((k&15)>>1 & 3), reg = (k&15)>>3,
// low half = even k.  weight row = nt*HDIM + jb*8 + (lane>>2);
// k pair base = c*64 + q*16 + (lane&3)*2 + reg*8.
// ---------------------------------------------------------------------------
__global__ __launch_bounds__(256) void wprep_kernel(const float* __restrict__ W,
                                                    int which) {
    int e = blockIdx.x * blockDim.x + threadIdx.x;
    if (e >= 2097152) return;
    uint32_t* hi = (which == 0) ? g_w0hi : (which == 1) ? g_w1ihi : g_w1hhi;
    uint32_t* lo = (which == 0) ? g_w0lo : (which == 1) ? g_w1ilo : g_w1hlo;
    int reg  = e & 1;
    int lane = (e >> 1) & 31;
    int nt   = (e >> 6) & 3;
    int q    = (e >> 8) & 3;
    int c    = (e >> 10) & 15;
    int jb   = e >> 14;
    int wrow = nt * HDIM + jb * 8 + (lane >> 2);
    int kb   = c * 64 + q * 16 + (lane & 3) * 2 + reg * 8;
    float w0 = W[(size_t)wrow * HDIM + kb];
    float w1 = W[(size_t)wrow * HDIM + kb + 1];
    float h0 = __half2float(__float2half_rn(w0));
    float h1 = __half2float(__float2half_rn(w1));
    hi[e] = packh2(h0, h1);
    lo[e] = packh2((w0 - h0) * LOSCALE, (w1 - h1) * LOSCALE);
}

// ---------------------------------------------------------------------------
// pre_gemm: 128x128x16 tiles, 8x8 microtile (validated; unchanged).
// ---------------------------------------------------------------------------
#define PGP 132

__global__ __launch_bounds__(256) void pre_gemm_kernel(
    const float* __restrict__ X, const float* __restrict__ W,
    const float* __restrict__ bi, const float* __restrict__ bh)
{
    __shared__ float As[16 * PGP];
    __shared__ float Bs[16 * PGP];

    const int m0 = blockIdx.y * 128;
    const int n0 = blockIdx.x * 128;
    const int tid = threadIdx.x;
    const int ty = tid >> 4, tx = tid & 15;

    float acc[8][8] = {};

    for (int k0 = 0; k0 < FDIM; k0 += 16) {
        if (tid < 128) {
            const float* src = &X[(size_t)(m0 + tid) * FDIM + k0];
            #pragma unroll
            for (int i = 0; i < 16; i += 4) {
                float4 v = *(const float4*)(src + i);
                As[(i + 0) * PGP + tid] = v.x;
                As[(i + 1) * PGP + tid] = v.y;
                As[(i + 2) * PGP + tid] = v.z;
                As[(i + 3) * PGP + tid] = v.w;
            }
        } else {
            int rb = tid - 128;
            const float* src = &W[(size_t)(n0 + rb) * FDIM + k0];
            #pragma unroll
            for (int i = 0; i < 16; i += 4) {
                float4 v = *(const float4*)(src + i);
                Bs[(i + 0) * PGP + rb] = v.x;
                Bs[(i + 1) * PGP + rb] = v.y;
                Bs[(i + 2) * PGP + rb] = v.z;
                Bs[(i + 3) * PGP + rb] = v.w;
            }
        }
        __syncthreads();

        #pragma unroll
        for (int kk = 0; kk < 16; kk++) {
            float a[8], b[8];
            *(float4*)&a[0] = *(const float4*)&As[kk * PGP + ty * 8];
            *(float4*)&a[4] = *(const float4*)&As[kk * PGP + ty * 8 + 4];
            *(float4*)&b[0] = *(const float4*)&Bs[kk * PGP + tx * 8];
            *(float4*)&b[4] = *(const float4*)&Bs[kk * PGP + tx * 8 + 4];
            #pragma unroll
            for (int i = 0; i < 8; i++)
                #pragma unroll
                for (int j = 0; j < 8; j++)
                    acc[i][j] += a[i] * b[j];
        }
        __syncthreads();
    }

    float bsum[8];
    #pragma unroll
    for (int j = 0; j < 8; j++) {
        int n = n0 + tx * 8 + j;
        bsum[j] = bi[n] + bh[n];
    }
    #pragma unroll
    for (int i = 0; i < 8; i++) {
        int m = m0 + ty * 8 + i;
        int bb = m >> 9, t = m & 511;
        float* dst = &g_pre0[((size_t)t * BSZ + bb) * G4H + n0 + tx * 8];
        float4 v0, v1;
        v0.x = acc[i][0] + bsum[0]; v0.y = acc[i][1] + bsum[1];
        v0.z = acc[i][2] + bsum[2]; v0.w = acc[i][3] + bsum[3];
        v1.x = acc[i][4] + bsum[4]; v1.y = acc[i][5] + bsum[5];
        v1.z = acc[i][6] + bsum[6]; v1.w = acc[i][7] + bsum[7];
        *(float4*)dst = v0;
        *(float4*)(dst + 4) = v1;
    }
}

// ---------------------------------------------------------------------------
// Recurrent GEMM: fp16 fragment-ordered operands, cp.async 2-stage, chunk K=64.
// Stage (uint32): [Ahi 2048][Alo 2048][Bhi 1024][Blo 1024] = 6144 (24 KB)
// ---------------------------------------------------------------------------
__device__ __forceinline__ void chunk_src(
    int p, int half64,
    const uint32_t* Ah0, const uint32_t* Al0, const uint32_t* Bh0, const uint32_t* Bl0,
    const uint32_t* Ah1, const uint32_t* Al1, const uint32_t* Bh1, const uint32_t* Bl1,
    const uint32_t*& ah, const uint32_t*& al, const uint32_t*& bh, const uint32_t*& bl)
{
    if (p < half64) {
        ah = Ah0 + (size_t)p * 2048; al = Al0 + (size_t)p * 2048;
        bh = Bh0 + (size_t)p * 1024; bl = Bl0 + (size_t)p * 1024;
    } else {
        int q = p - half64;
        ah = Ah1 + (size_t)q * 2048; al = Al1 + (size_t)q * 2048;
        bh = Bh1 + (size_t)q * 1024; bl = Bl1 + (size_t)q * 1024;
    }
}

__device__ __forceinline__ void stage_chunk(
    uint32_t sbase, int st, int tid,
    const uint32_t* ah, const uint32_t* al, const uint32_t* bh, const uint32_t* bl)
{
    uint32_t s = sbase + st * 24576;
    #pragma unroll
    for (int i = 0; i < 2; i++)
        cpa16(s + (tid + i * 256) * 16, ah + (tid + i * 256) * 4);
    #pragma unroll
    for (int i = 0; i < 2; i++)
        cpa16(s + 8192 + (tid + i * 256) * 16, al + (tid + i * 256) * 4);
    cpa16(s + 16384 + tid * 16, bh + tid * 4);
    cpa16(s + 20480 + tid * 16, bl + tid * 4);
}

// C = sum over chunks; Cm += Ah*Bh ; Cl += Ah*Bl' + Al'*Bh  (lo scaled 2^12)
__device__ __forceinline__ void gemm_f16(
    float Cm[2][4], float Cl[2][4],
    const uint32_t* Ah0, const uint32_t* Al0, const uint32_t* Bh0, const uint32_t* Bl0,
    const uint32_t* Ah1, const uint32_t* Al1, const uint32_t* Bh1, const uint32_t* Bl1,
    int n64, int half64, int tid, int mg, int ntbase,
    uint32_t* smu, uint32_t sbase)
{
    const int ln = tid & 31;
    const uint32_t *ah, *al, *bh, *bl;

    chunk_src(0, half64, Ah0, Al0, Bh0, Bl0, Ah1, Al1, Bh1, Bl1, ah, al, bh, bl);
    stage_chunk(sbase, 0, tid, ah, al, bh, bl);
    cp_commit();

    for (int p = 0; p < n64; p++) {
        if (p + 1 < n64) {
            chunk_src(p + 1, half64, Ah0, Al0, Bh0, Bl0, Ah1, Al1, Bh1, Bl1,
                      ah, al, bh, bl);
            stage_chunk(sbase, (p + 1) & 1, tid, ah, al, bh, bl);
            cp_commit();
            cp_wait<1>();
        } else {
            cp_wait<0>();
        }
        __syncthreads();

        const uint32_t* sb = smu + (p & 1) * 6144;
        #pragma unroll
        for (int q = 0; q < 4; q++) {
            uint4 fah = *(const uint4*)(sb + (q * 4 + mg) * 128 + ln * 4);
            uint4 fal = *(const uint4*)(sb + 2048 + (q * 4 + mg) * 128 + ln * 4);
            #pragma unroll
            for (int s = 0; s < 2; s++) {
                int nt = ntbase + s;
                uint2 fbh = *(const uint2*)(sb + 4096 + (q * 4 + nt) * 64 + ln * 2);
                uint2 fbl = *(const uint2*)(sb + 5120 + (q * 4 + nt) * 64 + ln * 2);
                mma16(Cm[s], fah, fbh);
                mma16(Cl[s], fah, fbl);
                mma16(Cl[s], fal, fbh);
            }
        }
        __syncthreads();
    }
}

// ---------------------------------------------------------------------------
// Persistent recurrence kernel
// ---------------------------------------------------------------------------
__global__ __launch_bounds__(256, 1) void lstm_persistent_kernel(
    const float* __restrict__ bi1, const float* __restrict__ bh1,
    float* __restrict__ out)
{
    extern __shared__ uint32_t smu[];            // 2*6144 stage + gbuf
    float* gbuf = (float*)(smu + 12288);         // 64*33 floats
    uint32_t sbase = (uint32_t)__cvta_generic_to_shared(smu);

    const int j0  = blockIdx.x * 8;
    const int tid = threadIdx.x;
    const int w   = tid >> 5;
    const int ln  = tid & 31;
    const int g   = ln >> 2;
    const int tg  = ln & 3;
    const int mg  = w & 3;
    const int ntbase = (w >> 2) * 2;
    const int mrow = mg * 16 + g;
    const int cbase = ntbase * 8;
    const size_t jbo = (size_t)blockIdx.x * 16384;   // weight offset per jb

    unsigned gen = atomicAdd(&g_bar_gen, 0u);

    // ---- init own state slice: 256 threads cover 512 cells as 256 half2 ----
    {
        int cell0 = tid * 2;
        int b = cell0 >> 3, jj = cell0 & 7;
        int j = j0 + jj;
        int fi = afrag_u32(b, j);
        g_h0hi[0][fi] = 0u; g_h0lo[0][fi] = 0u;
        g_h1hi[0][fi] = 0u; g_h1lo[0][fi] = 0u;
        g_c0[b * HDIM + j] = 0.f; g_c0[b * HDIM + j + 1] = 0.f;
        g_c1[b * HDIM + j] = 0.f; g_c1[b * HDIM + j + 1] = 0.f;
    }
    grid_bar(gen);

    // ---- layer-1 bias sums ----
    float bsum[2][4];
    #pragma unroll
    for (int u = 0; u < 2; u++) {
        int jj = (tid * 2 + u) & 7;
        #pragma unroll
        for (int gt = 0; gt < 4; gt++)
            bsum[u][gt] = bi1[gt * HDIM + j0 + jj] + bh1[gt * HDIM + j0 + jj];
    }

    for (int t = 0; t < TLEN; t++) {
        // ======================= layer 0 =======================
        const uint32_t* Ah = g_h0hi[t & 1];
        const uint32_t* Al = g_h0lo[t & 1];

        float prev[2][4];
        {
            const float* pre = &g_pre0[(size_t)t * BSZ * G4H];
            #pragma unroll
            for (int u = 0; u < 2; u++) {
                int cell = tid * 2 + u;
                int b = cell >> 3, jj = cell & 7;
                #pragma unroll
                for (int gt = 0; gt < 4; gt++)
                    prev[u][gt] = pre[(size_t)b * G4H + gt * HDIM + j0 + jj];
            }
        }

        float Cm[2][4] = {}, Cl[2][4] = {};
        gemm_f16(Cm, Cl, Ah, Al, g_w0hi + jbo, g_w0lo + jbo,
                         Ah, Al, g_w0hi + jbo, g_w0lo + jbo,
                 16, 16, tid, mg, ntbase, smu, sbase);

        #pragma unroll
        for (int s = 0; s < 2; s++) {
            int col = cbase + s * 8 + 2 * tg;
            gbuf[mrow * 33 + col]           = Cm[s][0] + Cl[s][0] * LOINV;
            gbuf[mrow * 33 + col + 1]       = Cm[s][1] + Cl[s][1] * LOINV;
            gbuf[(mrow + 8) * 33 + col]     = Cm[s][2] + Cl[s][2] * LOINV;
            gbuf[(mrow + 8) * 33 + col + 1] = Cm[s][3] + Cl[s][3] * LOINV;
        }
        __syncthreads();

        {
            int cell0 = tid * 2;
            int b = cell0 >> 3, jj = cell0 & 7;   // jj even
            int j = j0 + jj;
            float hv[2];
            #pragma unroll
            for (int u = 0; u < 2; u++) {
                float ig = gbuf[b * 33 + jj + u]      + prev[u][0];
                float fg = gbuf[b * 33 + 8 + jj + u]  + prev[u][1];
                float gg = gbuf[b * 33 + 16 + jj + u] + prev[u][2];
                float og = gbuf[b * 33 + 24 + jj + u] + prev[u][3];
                float c_old = g_c0[b * HDIM + j + u];
                float cn = sigf(fg) * c_old + sigf(ig) * tanhf(gg);
                hv[u] = sigf(og) * tanhf(cn);
                g_c0[b * HDIM + j + u] = cn;
                g_h0e[b * HDIM + j + u] = hv[u];
            }
            float h0 = __half2float(__float2half_rn(hv[0]));
            float h1 = __half2float(__float2half_rn(hv[1]));
            int fi = afrag_u32(b, j);
            g_h0hi[(t + 1) & 1][fi] = packh2(h0, h1);
            g_h0lo[(t + 1) & 1][fi] = packh2((hv[0] - h0) * LOSCALE,
                                             (hv[1] - h1) * LOSCALE);
        }
        grid_bar(gen);   // h0(t) / h1(t-1) fragments visible before layer 1

        // ======================= layer 1 =======================
        const uint32_t* A0h = g_h0hi[(t + 1) & 1];
        const uint32_t* A0l = g_h0lo[(t + 1) & 1];
        const uint32_t* A1h = g_h1hi[t & 1];
        const uint32_t* A1l = g_h1lo[t & 1];

        float Cm2[2][4] = {}, Cl2[2][4] = {};
        gemm_f16(Cm2, Cl2, A0h, A0l, g_w1ihi + jbo, g_w1ilo + jbo,
                           A1h, A1l, g_w1hhi + jbo, g_w1hlo + jbo,
                 32, 16, tid, mg, ntbase, smu, sbase);

        #pragma unroll
        for (int s = 0; s < 2; s++) {
            int col = cbase + s * 8 + 2 * tg;
            gbuf[mrow * 33 + col]           = Cm2[s][0] + Cl2[s][0] * LOINV;
            gbuf[mrow * 33 + col + 1]       = Cm2[s][1] + Cl2[s][1] * LOINV;
            gbuf[(mrow + 8) * 33 + col]     = Cm2[s][2] + Cl2[s][2] * LOINV;
            gbuf[(mrow + 8) * 33 + col + 1] = Cm2[s][3] + Cl2[s][3] * LOINV;
        }
        __syncthreads();

        {
            int cell0 = tid * 2;
            int b = cell0 >> 3, jj = cell0 & 7;
            int j = j0 + jj;
            float hv[2];
            #pragma unroll
            for (int u = 0; u < 2; u++) {
                float ig = gbuf[b * 33 + jj + u]      + bsum[u][0];
                float fg = gbuf[b * 33 + 8 + jj + u]  + bsum[u][1];
                float gg = gbuf[b * 33 + 16 + jj + u] + bsum[u][2];
                float og = gbuf[b * 33 + 24 + jj + u] + bsum[u][3];
                float c_old = g_c1[b * HDIM + j + u];
                float cn = sigf(fg) * c_old + sigf(ig) * tanhf(gg);
                hv[u] = sigf(og) * tanhf(cn);
                g_c1[b * HDIM + j + u] = cn;
                g_h1e[b * HDIM + j + u] = hv[u];
                out[((size_t)b * TLEN + t) * HDIM + j + u] = hv[u];
            }
            float h0 = __half2float(__float2half_rn(hv[0]));
            float h1 = __half2float(__float2half_rn(hv[1]));
            int fi = afrag_u32(b, j);
            g_h1hi[(t + 1) & 1][fi] = packh2(h0, h1);
            g_h1lo[(t + 1) & 1][fi] = packh2((hv[0] - h0) * LOSCALE,
                                             (hv[1] - h1) * LOSCALE);
        }
        __syncthreads();   // gbuf reuse; cross-CTA ordered by next barrier
    }

    // ---- pack final states (T even -> buffers [0]) ----
    const size_t BH   = (size_t)BSZ * HDIM;
    const size_t base = (size_t)BSZ * TLEN * HDIM;
    for (int u = tid; u < 64 * 8; u += 256) {
        int b = u >> 3, jj = u & 7;
        int idx = b * HDIM + j0 + jj;
        out[base + idx]          = g_h0e[idx];
        out[base + BH + idx]     = g_h1e[idx];
        out[base + 2 * BH + idx] = g_c0[idx];
        out[base + 3 * BH + idx] = g_c1[idx];
    }
}

// ---------------------------------------------------------------------------
// Launch (graph-capturable; few nodes)
// ---------------------------------------------------------------------------
extern "C" void kernel_launch(void* const* d_in, const int* in_sizes, int n_in,
                              void* d_out, int out_size)
{
    (void)in_sizes; (void)n_in; (void)out_size;
    const float* x    = (const float*)d_in[0];
    const float* Wih0 = (const float*)d_in[1];
    const float* Whh0 = (const float*)d_in[2];
    const float* bih0 = (const float*)d_in[3];
    const float* bhh0 = (const float*)d_in[4];
    const float* Wih1 = (const float*)d_in[5];
    const float* Whh1 = (const float*)d_in[6];
    const float* bih1 = (const float*)d_in[7];
    const float* bhh1 = (const float*)d_in[8];
    float* out = (float*)d_out;

    const int smem_bytes = (2 * 6144 + 2112) * 4;   // 57600
    cudaFuncSetAttribute(lstm_persistent_kernel,
                         cudaFuncAttributeMaxDynamicSharedMemorySize, smem_bytes);

    // per-launch weight prep (deterministic)
    wprep_kernel<<<8192, 256>>>(Whh0, 0);
    wprep_kernel<<<8192, 256>>>(Wih1, 1);
    wprep_kernel<<<8192, 256>>>(Whh1, 2);

    dim3 pre_grid(G4H / 128, (BSZ * TLEN) / 128);    // 32 x 256
    pre_gemm_kernel<<<pre_grid, 256>>>(x, Wih0, bih0, bhh0);

    lstm_persistent_kernel<<<NCTA, 256, smem_bytes>>>(bih1, bhh1, out);
}